// round 1
// baseline (speedup 1.0000x reference)
#include <cuda_runtime.h>
#include <math.h>
#include <float.h>

#define B_    16
#define NPTS  4096

// ---------------- scratch (static device globals; no allocation at runtime) ----
__device__ float g_h1[(size_t)B_ * 64  * NPTS];
__device__ float g_h2[(size_t)B_ * 128 * NPTS];
__device__ float g_h3[(size_t)B_ * 256 * NPTS];
__device__ float g_h4[(size_t)B_ * 512 * NPTS];
__device__ float g_h5[(size_t)B_ * 256 * NPTS];
__device__ float g_h6[(size_t)B_ * 128 * NPTS];
__device__ float g_G [(size_t)65536 * 512];   // gathered softpool matrix, [k=c*256+w][col=b*32+h]
__device__ float g_P8[(size_t)16 * 256 * 512]; // split-K partials for conv8
__device__ float g_y8[256 * 512];              // conv8 out, [o][b*32+h]
__device__ float g_y9[B_ * 512];               // conv9 out (256 used)
__device__ float g_gcon[B_ * 512];             // glob contribution to conv4
__device__ int   g_idx[B_ * 256 * 32];         // top-k indices
__device__ float g_scale[512];
__device__ float g_shift[512];

// ---------------- generic batched GEMM: Y[b,o,n] = sum_k W[o,k]*X[b,k,n] (+bias) --
// 64x64 output tile, BK=16, 256 threads, 4x4 per thread. O, N multiples of 64.
// ksplit > 1: blockIdx.z = chunk (B must be 1 logically), writes partials w/o bias.
__global__ void gemm_kernel(const float* __restrict__ X, const float* __restrict__ W,
                            const float* __restrict__ bias, const float* __restrict__ biasBO,
                            float* __restrict__ Y,
                            int O, int K, int N, int ldw, int ksplit)
{
    __shared__ float As[16][66];  // [k][m], padded
    __shared__ float Bs[16][64];  // [k][n]

    int bz    = blockIdx.z;
    int b     = bz / ksplit;
    int chunk = bz % ksplit;
    int Kc    = K / ksplit;         // K divisible by ksplit in all uses
    int kbeg  = chunk * Kc;
    int kend  = kbeg + Kc;

    int o0 = blockIdx.y * 64;
    int n0 = blockIdx.x * 64;
    const float* Xb = X + (size_t)b * K * N;

    int tid = threadIdx.x;
    int tm  = tid >> 4;   // 0..15
    int tn  = tid & 15;   // 0..15

    float acc[4][4] = {};

    for (int k0 = kbeg; k0 < kend; k0 += 16) {
        #pragma unroll
        for (int i = 0; i < 4; i++) {
            int e = tid + i * 256;
            int m = e >> 4, k = e & 15;
            As[k][m] = (k0 + k < K) ? W[(size_t)(o0 + m) * ldw + k0 + k] : 0.f;
        }
        #pragma unroll
        for (int i = 0; i < 4; i++) {
            int e = tid + i * 256;
            int k = e >> 6, n = e & 63;
            Bs[k][n] = (k0 + k < K) ? Xb[(size_t)(k0 + k) * N + n0 + n] : 0.f;
        }
        __syncthreads();
        #pragma unroll
        for (int kk = 0; kk < 16; kk++) {
            float a[4], bb[4];
            #pragma unroll
            for (int i = 0; i < 4; i++) a[i]  = As[kk][tm * 4 + i];
            #pragma unroll
            for (int j = 0; j < 4; j++) bb[j] = Bs[kk][tn * 4 + j];
            #pragma unroll
            for (int i = 0; i < 4; i++)
                #pragma unroll
                for (int j = 0; j < 4; j++)
                    acc[i][j] += a[i] * bb[j];
        }
        __syncthreads();
    }

    #pragma unroll
    for (int i = 0; i < 4; i++) {
        int o = o0 + tm * 4 + i;
        float bv = 0.f;
        if (ksplit == 1) {
            if (bias)   bv += bias[o];
            if (biasBO) bv += biasBO[b * O + o];
        }
        size_t base = (ksplit == 1) ? ((size_t)(b * O + o) * N)
                                    : ((size_t)(chunk * O + o) * N);
        #pragma unroll
        for (int j = 0; j < 4; j++)
            Y[base + n0 + tn * 4 + j] = acc[i][j] + bv;
    }
}

// ---------------- BN training-mode statistics: scale/shift per channel ----------
__global__ void stats_kernel(const float* __restrict__ X, const float* __restrict__ g,
                             const float* __restrict__ be,
                             float* __restrict__ scale, float* __restrict__ shift, int C)
{
    int c = blockIdx.x;
    float s = 0.f, s2 = 0.f;
    for (int t = threadIdx.x; t < B_ * NPTS; t += blockDim.x) {
        int b = t >> 12;
        int n = t & (NPTS - 1);
        float v = X[((size_t)(b * C + c)) * NPTS + n];
        s += v; s2 += v * v;
    }
    __shared__ float sh1[256], sh2[256];
    sh1[threadIdx.x] = s; sh2[threadIdx.x] = s2;
    __syncthreads();
    for (int st = 128; st > 0; st >>= 1) {
        if (threadIdx.x < st) {
            sh1[threadIdx.x] += sh1[threadIdx.x + st];
            sh2[threadIdx.x] += sh2[threadIdx.x + st];
        }
        __syncthreads();
    }
    if (threadIdx.x == 0) {
        const float inv = 1.f / (float)(B_ * NPTS);
        float m  = sh1[0] * inv;
        float v  = sh2[0] * inv - m * m;
        float sc = g[c] / sqrtf(v + 1e-5f);
        scale[c] = sc;
        shift[c] = be[c] - m * sc;
    }
}

__global__ void apply_kernel(float* __restrict__ X, const float* __restrict__ scale,
                             const float* __restrict__ shift, int C, int relu)
{
    size_t i = (size_t)blockIdx.x * blockDim.x + threadIdx.x;
    int c = (int)((i >> 12) % (size_t)C);
    float v = X[i] * scale[c] + shift[c];
    if (relu) v = fmaxf(v, 0.f);
    X[i] = v;
}

// ---------------- exact top-32 (desc, lower-index tie-break) per (b,c) row -------
__global__ void topk_kernel(const float* __restrict__ X, int* __restrict__ idx_out)
{
    int bc = blockIdx.x;                 // b*256 + c
    const float* row = X + (size_t)bc * NPTS;
    int tid = threadIdx.x;               // 256 threads

    float v[16];
    #pragma unroll
    for (int j = 0; j < 16; j++) v[j] = row[j * 256 + tid];

    __shared__ float swv[8];
    __shared__ int   swi[8];
    __shared__ int   sbi;

    for (int iter = 0; iter < 32; iter++) {
        float lv = -FLT_MAX; int li = 0x7fffffff;
        #pragma unroll
        for (int j = 0; j < 16; j++) {
            int n = j * 256 + tid;
            if (v[j] > lv || (v[j] == lv && n < li)) { lv = v[j]; li = n; }
        }
        #pragma unroll
        for (int off = 16; off > 0; off >>= 1) {
            float ov = __shfl_down_sync(0xffffffff, lv, off);
            int   oi = __shfl_down_sync(0xffffffff, li, off);
            if (ov > lv || (ov == lv && oi < li)) { lv = ov; li = oi; }
        }
        if ((tid & 31) == 0) { swv[tid >> 5] = lv; swi[tid >> 5] = li; }
        __syncthreads();
        if (tid == 0) {
            float gv = swv[0]; int gi = swi[0];
            #pragma unroll
            for (int w = 1; w < 8; w++)
                if (swv[w] > gv || (swv[w] == gv && swi[w] < gi)) { gv = swv[w]; gi = swi[w]; }
            sbi = gi;
            idx_out[bc * 32 + iter] = gi;
        }
        __syncthreads();
        int gi = sbi;
        if ((gi & 255) == tid) v[gi >> 8] = -FLT_MAX;
        __syncthreads();
    }
}

// ---------------- softpool gather: G[(c*256+w)*512 + b*32+h] = h3[b,c,idx[b,w,h]] --
__global__ void gather_kernel(const float* __restrict__ h3, const int* __restrict__ idx,
                              float* __restrict__ G)
{
    size_t i = (size_t)blockIdx.x * blockDim.x + threadIdx.x;   // 65536*512 total
    int col = (int)(i & 511);
    size_t k = i >> 9;
    int b = col >> 5, h = col & 31;
    int c = (int)(k >> 8), w = (int)(k & 255);
    int n = idx[((b << 8) + w) * 32 + h];
    G[i] = h3[(((size_t)(b * 256 + c)) << 12) + n];
}

// ---------------- conv8 split-K reduce -------------------------------------------
__global__ void reduce8_kernel(const float* __restrict__ P, const float* __restrict__ b8,
                               float* __restrict__ y8)
{
    int i = blockIdx.x * blockDim.x + threadIdx.x;   // 256*512
    float s = b8[i >> 9];
    #pragma unroll
    for (int ch = 0; ch < 16; ch++) s += P[(size_t)ch * 131072 + i];
    y8[i] = s;
}

// ---------------- conv9: y9[b,o] = b9[o] + sum_{c,h} y8[c, b*32+h]*w9[o,c,h] ------
__global__ void conv9_kernel(const float* __restrict__ y8, const float* __restrict__ w9,
                             const float* __restrict__ b9, float* __restrict__ y9)
{
    int b = blockIdx.x >> 8;
    int o = blockIdx.x & 255;
    int c = threadIdx.x;    // 256
    float s = 0.f;
    const float* yb = y8 + (size_t)c * 512 + b * 32;
    const float* wr = w9 + ((size_t)o * 256 + c) * 32;
    #pragma unroll
    for (int h = 0; h < 32; h++) s += yb[h] * wr[h];
    __shared__ float sh[256];
    sh[c] = s; __syncthreads();
    for (int st = 128; st > 0; st >>= 1) {
        if (c < st) sh[c] += sh[c + st];
        __syncthreads();
    }
    if (c == 0) y9[b * 256 + o] = sh[0] + b9[o];
}

// ---------------- glob contribution to conv4: gcon[b,o] = sum_c w4[o,c]*y9[b,c] ---
__global__ void gcon_kernel(const float* __restrict__ w4, const float* __restrict__ y9,
                            float* __restrict__ gcon)
{
    int i = blockIdx.x * blockDim.x + threadIdx.x;   // 16*512
    int b = i >> 9, o = i & 511;
    float s = 0.f;
    for (int c = 0; c < 256; c++) s += w4[o * 320 + c] * y9[b * 256 + c];
    gcon[i] = s;
}

// ---------------- conv7 + tanh ----------------------------------------------------
__global__ void conv7_kernel(const float* __restrict__ h6, const float* __restrict__ w7,
                             const float* __restrict__ b7, float* __restrict__ out)
{
    int i = blockIdx.x * blockDim.x + threadIdx.x;   // B*NPTS
    int b = i >> 12, n = i & (NPTS - 1);
    float s0 = b7[0], s1 = b7[1], s2 = b7[2];
    const float* hb = h6 + (((size_t)b * 128) << 12) + n;
    for (int c = 0; c < 128; c++) {
        float v = hb[(size_t)c * NPTS];
        s0 += w7[c] * v;
        s1 += w7[128 + c] * v;
        s2 += w7[256 + c] * v;
    }
    out[((size_t)(b * 3 + 0)) * NPTS + n] = tanhf(s0);
    out[((size_t)(b * 3 + 1)) * NPTS + n] = tanhf(s1);
    out[((size_t)(b * 3 + 2)) * NPTS + n] = tanhf(s2);
}

// ===================================================================================
extern "C" void kernel_launch(void* const* d_in, const int* in_sizes, int n_in,
                              void* d_out, int out_size)
{
    const float* x   = (const float*)d_in[0];
    const float* w1  = (const float*)d_in[1];
    const float* b1  = (const float*)d_in[2];
    const float* g1  = (const float*)d_in[3];
    const float* be1 = (const float*)d_in[4];
    const float* w2  = (const float*)d_in[5];
    const float* b2  = (const float*)d_in[6];
    const float* g2  = (const float*)d_in[7];
    const float* be2 = (const float*)d_in[8];
    const float* w3  = (const float*)d_in[9];
    const float* b3  = (const float*)d_in[10];
    const float* g3  = (const float*)d_in[11];
    const float* be3 = (const float*)d_in[12];
    const float* w4  = (const float*)d_in[13];
    const float* b4  = (const float*)d_in[14];
    const float* g4  = (const float*)d_in[15];
    const float* be4 = (const float*)d_in[16];
    const float* w5  = (const float*)d_in[17];
    const float* b5  = (const float*)d_in[18];
    const float* g5  = (const float*)d_in[19];
    const float* be5 = (const float*)d_in[20];
    const float* w6  = (const float*)d_in[21];
    const float* b6  = (const float*)d_in[22];
    const float* g6  = (const float*)d_in[23];
    const float* be6 = (const float*)d_in[24];
    const float* w7  = (const float*)d_in[25];
    const float* b7  = (const float*)d_in[26];
    const float* w8  = (const float*)d_in[27];
    const float* b8  = (const float*)d_in[28];
    const float* w9  = (const float*)d_in[29];
    const float* b9  = (const float*)d_in[30];
    float* out = (float*)d_out;

    float *h1, *h2, *h3, *h4, *h5, *h6, *G, *P8, *y8, *y9, *gcon, *scale, *shift;
    int* idxp;
    cudaGetSymbolAddress((void**)&h1,    g_h1);
    cudaGetSymbolAddress((void**)&h2,    g_h2);
    cudaGetSymbolAddress((void**)&h3,    g_h3);
    cudaGetSymbolAddress((void**)&h4,    g_h4);
    cudaGetSymbolAddress((void**)&h5,    g_h5);
    cudaGetSymbolAddress((void**)&h6,    g_h6);
    cudaGetSymbolAddress((void**)&G,     g_G);
    cudaGetSymbolAddress((void**)&P8,    g_P8);
    cudaGetSymbolAddress((void**)&y8,    g_y8);
    cudaGetSymbolAddress((void**)&y9,    g_y9);
    cudaGetSymbolAddress((void**)&gcon,  g_gcon);
    cudaGetSymbolAddress((void**)&idxp,  g_idx);
    cudaGetSymbolAddress((void**)&scale, g_scale);
    cudaGetSymbolAddress((void**)&shift, g_shift);

    const int NB = NPTS / 64;   // 64 tile-columns over points

    // conv1 (4->64) + BN + relu
    gemm_kernel<<<dim3(NB, 1, B_), 256>>>(x, w1, b1, nullptr, h1, 64, 4, NPTS, 4, 1);
    stats_kernel<<<64, 256>>>(h1, g1, be1, scale, shift, 64);
    apply_kernel<<<(B_ * 64 * NPTS) / 256, 256>>>(h1, scale, shift, 64, 1);

    // conv2 (64->128) + BN + relu
    gemm_kernel<<<dim3(NB, 2, B_), 256>>>(h1, w2, b2, nullptr, h2, 128, 64, NPTS, 64, 1);
    stats_kernel<<<128, 256>>>(h2, g2, be2, scale, shift, 128);
    apply_kernel<<<(B_ * 128 * NPTS) / 256, 256>>>(h2, scale, shift, 128, 1);

    // conv3 (128->256) + BN (no relu)
    gemm_kernel<<<dim3(NB, 4, B_), 256>>>(h2, w3, b3, nullptr, h3, 256, 128, NPTS, 128, 1);
    stats_kernel<<<256, 256>>>(h3, g3, be3, scale, shift, 256);
    apply_kernel<<<(B_ * 256 * NPTS) / 256, 256>>>(h3, scale, shift, 256, 0);

    // top-32 per (b, sort channel), then gather softpool matrix
    topk_kernel<<<B_ * 256, 256>>>(h3, idxp);
    gather_kernel<<<(int)(((size_t)65536 * 512) / 256), 256>>>(h3, idxp, G);

    // conv8: y8[o, b*32+h] = sum_{k=c*256+w} w8[o,k] * G[k, col]   (split-K 16)
    gemm_kernel<<<dim3(512 / 64, 256 / 64, 16), 256>>>(G, w8, nullptr, nullptr, P8,
                                                       256, 65536, 512, 65536, 16);
    reduce8_kernel<<<(256 * 512) / 256, 256>>>(P8, b8, y8);

    // conv9 -> global feature y9[b,o]
    conv9_kernel<<<B_ * 256, 256>>>(y8, w9, b9, y9);

    // fold glob part of conv4 into per-(b,o) bias
    gcon_kernel<<<(B_ * 512) / 256, 256>>>(w4, y9, gcon);

    // conv4 (pointfeat 64 -> 512, + gcon + b4) + BN + relu
    gemm_kernel<<<dim3(NB, 8, B_), 256>>>(h1, w4 + 256, b4, gcon, h4, 512, 64, NPTS, 320, 1);
    stats_kernel<<<512, 256>>>(h4, g4, be4, scale, shift, 512);
    apply_kernel<<<(B_ * 512 * NPTS) / 256, 256>>>(h4, scale, shift, 512, 1);

    // conv5 (512->256) + BN + relu
    gemm_kernel<<<dim3(NB, 4, B_), 256>>>(h4, w5, b5, nullptr, h5, 256, 512, NPTS, 512, 1);
    stats_kernel<<<256, 256>>>(h5, g5, be5, scale, shift, 256);
    apply_kernel<<<(B_ * 256 * NPTS) / 256, 256>>>(h5, scale, shift, 256, 1);

    // conv6 (256->128) + BN + relu
    gemm_kernel<<<dim3(NB, 2, B_), 256>>>(h5, w6, b6, nullptr, h6, 128, 256, NPTS, 256, 1);
    stats_kernel<<<128, 256>>>(h6, g6, be6, scale, shift, 128);
    apply_kernel<<<(B_ * 128 * NPTS) / 256, 256>>>(h6, scale, shift, 128, 1);

    // conv7 (128->3) + tanh
    conv7_kernel<<<(B_ * NPTS) / 256, 256>>>(h6, w7, b7, out);
}

// round 2
// speedup vs baseline: 1.4258x; 1.4258x over previous
#include <cuda_runtime.h>
#include <math.h>
#include <float.h>
#include <stdint.h>

#define B_    16
#define NPTS  4096

// ---------------- scratch (static device globals; no allocation at runtime) ----
__device__ float g_h1[(size_t)B_ * 64  * NPTS];
__device__ float g_h2[(size_t)B_ * 128 * NPTS];
__device__ float g_h3[(size_t)B_ * 256 * NPTS];
__device__ float g_h4[(size_t)B_ * 512 * NPTS];
__device__ float g_h5[(size_t)B_ * 256 * NPTS];
__device__ float g_h6[(size_t)B_ * 128 * NPTS];
__device__ float g_G [(size_t)65536 * 512];   // gathered softpool matrix, [k=c*256+w][col=b*32+h]
__device__ float g_P8[(size_t)16 * 256 * 512]; // split-K partials for conv8
__device__ float g_y8[256 * 512];              // conv8 out, [o][b*32+h]
__device__ float g_y9[B_ * 512];               // conv9 out (256 used)
__device__ float g_gcon[B_ * 512];             // glob contribution to conv4
__device__ int   g_idx[B_ * 256 * 32];         // top-k indices
__device__ float g_scale[512];
__device__ float g_shift[512];

// ---------------- fp32 SGEMM (exact; used for conv1-3 which feed top-k) ----------
__global__ void gemm_kernel(const float* __restrict__ X, const float* __restrict__ W,
                            const float* __restrict__ bias, const float* __restrict__ biasBO,
                            float* __restrict__ Y,
                            int O, int K, int N, int ldw, int ksplit)
{
    __shared__ float As[16][66];  // [k][m], padded
    __shared__ float Bs[16][64];  // [k][n]

    int bz    = blockIdx.z;
    int b     = bz / ksplit;
    int chunk = bz % ksplit;
    int Kc    = K / ksplit;
    int kbeg  = chunk * Kc;
    int kend  = kbeg + Kc;

    int o0 = blockIdx.y * 64;
    int n0 = blockIdx.x * 64;
    const float* Xb = X + (size_t)b * K * N;

    int tid = threadIdx.x;
    int tm  = tid >> 4;
    int tn  = tid & 15;

    float acc[4][4] = {};

    for (int k0 = kbeg; k0 < kend; k0 += 16) {
        #pragma unroll
        for (int i = 0; i < 4; i++) {
            int e = tid + i * 256;
            int m = e >> 4, k = e & 15;
            As[k][m] = (k0 + k < K) ? W[(size_t)(o0 + m) * ldw + k0 + k] : 0.f;
        }
        #pragma unroll
        for (int i = 0; i < 4; i++) {
            int e = tid + i * 256;
            int k = e >> 6, n = e & 63;
            Bs[k][n] = (k0 + k < K) ? Xb[(size_t)(k0 + k) * N + n0 + n] : 0.f;
        }
        __syncthreads();
        #pragma unroll
        for (int kk = 0; kk < 16; kk++) {
            float a[4], bb[4];
            #pragma unroll
            for (int i = 0; i < 4; i++) a[i]  = As[kk][tm * 4 + i];
            #pragma unroll
            for (int j = 0; j < 4; j++) bb[j] = Bs[kk][tn * 4 + j];
            #pragma unroll
            for (int i = 0; i < 4; i++)
                #pragma unroll
                for (int j = 0; j < 4; j++)
                    acc[i][j] += a[i] * bb[j];
        }
        __syncthreads();
    }

    #pragma unroll
    for (int i = 0; i < 4; i++) {
        int o = o0 + tm * 4 + i;
        float bv = 0.f;
        if (ksplit == 1) {
            if (bias)   bv += bias[o];
            if (biasBO) bv += biasBO[b * O + o];
        }
        size_t base = (ksplit == 1) ? ((size_t)(b * O + o) * N)
                                    : ((size_t)(chunk * O + o) * N);
        #pragma unroll
        for (int j = 0; j < 4; j++)
            Y[base + n0 + tn * 4 + j] = acc[i][j] + bv;
    }
}

// ---------------- tf32 tensor-core GEMM -------------------------------------------
// Y[b,o,n] = sum_k W[o,k]*X[b,k,n] (+bias[o] +biasBO[b,o]).
// BM=64 (O), BN=64 (N), BK=16, 128 threads (4 warps, each 32x32), double-buffered.
// Requires O,N multiples of 64, K/ksplit multiple of 16, float4-aligned rows.
#define TFPAD 68

__device__ __forceinline__ uint32_t f2tf32(float f) {
    uint32_t u;
    asm("cvt.rna.tf32.f32 %0, %1;" : "=r"(u) : "f"(f));
    return u;
}
__device__ __forceinline__ float f2tf32f(float f) {
    return __uint_as_float(f2tf32(f));
}

__global__ void __launch_bounds__(128) gemm_tf32(
    const float* __restrict__ X, const float* __restrict__ W,
    const float* __restrict__ bias, const float* __restrict__ biasBO,
    float* __restrict__ Y, int O, int K, int N, int ldw, int ksplit)
{
    __shared__ float As[2][16][TFPAD];   // [k][m]
    __shared__ float Bs[2][16][TFPAD];   // [k][n]

    int bz    = blockIdx.z;
    int b     = bz / ksplit;
    int chunk = bz % ksplit;
    int Kc    = K / ksplit;
    int kbeg  = chunk * Kc;

    int o0 = blockIdx.y * 64;
    int n0 = blockIdx.x * 64;
    const float* Xb = X + (size_t)b * K * N;

    int tid  = threadIdx.x;
    int lane = tid & 31;
    int warp = tid >> 5;
    int wm   = (warp & 1) * 32;
    int wn   = (warp >> 1) * 32;
    int gid  = lane >> 2;
    int tig  = lane & 3;

    // global-load assignments
    int mA = tid & 63;
    int qA = (tid >> 6) * 2;          // quads qA, qA+1 (each quad = 4 k's)
    const float* wp = W + (size_t)(o0 + mA) * ldw;
    int n4 = (tid & 15) * 4;
    int kr = tid >> 4;                // 0..7 -> rows kr, kr+8

    float acc[2][4][4] = {};
    float4 ra0, ra1, rb0, rb1;

    // prologue fetch + store stage 0
    {
        int k0 = kbeg;
        ra0 = *(const float4*)(wp + k0 + qA * 4);
        ra1 = *(const float4*)(wp + k0 + qA * 4 + 4);
        rb0 = *(const float4*)(Xb + (size_t)(k0 + kr) * N + n0 + n4);
        rb1 = *(const float4*)(Xb + (size_t)(k0 + kr + 8) * N + n0 + n4);
        As[0][qA*4+0][mA] = f2tf32f(ra0.x);
        As[0][qA*4+1][mA] = f2tf32f(ra0.y);
        As[0][qA*4+2][mA] = f2tf32f(ra0.z);
        As[0][qA*4+3][mA] = f2tf32f(ra0.w);
        As[0][qA*4+4][mA] = f2tf32f(ra1.x);
        As[0][qA*4+5][mA] = f2tf32f(ra1.y);
        As[0][qA*4+6][mA] = f2tf32f(ra1.z);
        As[0][qA*4+7][mA] = f2tf32f(ra1.w);
        float4 c0 = make_float4(f2tf32f(rb0.x), f2tf32f(rb0.y), f2tf32f(rb0.z), f2tf32f(rb0.w));
        float4 c1 = make_float4(f2tf32f(rb1.x), f2tf32f(rb1.y), f2tf32f(rb1.z), f2tf32f(rb1.w));
        *(float4*)&Bs[0][kr][n4]     = c0;
        *(float4*)&Bs[0][kr + 8][n4] = c1;
    }
    __syncthreads();

    int nIter = Kc / 16;
    for (int it = 0; it < nIter; it++) {
        int s = it & 1;
        bool more = (it + 1 < nIter);
        if (more) {
            int k0 = kbeg + (it + 1) * 16;
            ra0 = *(const float4*)(wp + k0 + qA * 4);
            ra1 = *(const float4*)(wp + k0 + qA * 4 + 4);
            rb0 = *(const float4*)(Xb + (size_t)(k0 + kr) * N + n0 + n4);
            rb1 = *(const float4*)(Xb + (size_t)(k0 + kr + 8) * N + n0 + n4);
        }

        #pragma unroll
        for (int ks = 0; ks < 2; ks++) {
            int kk = ks * 8;
            uint32_t a[2][4], bf[4][2];
            #pragma unroll
            for (int i = 0; i < 2; i++) {
                int mr = wm + i * 16 + gid;
                a[i][0] = __float_as_uint(As[s][kk + tig    ][mr    ]);
                a[i][1] = __float_as_uint(As[s][kk + tig    ][mr + 8]);
                a[i][2] = __float_as_uint(As[s][kk + tig + 4][mr    ]);
                a[i][3] = __float_as_uint(As[s][kk + tig + 4][mr + 8]);
            }
            #pragma unroll
            for (int j = 0; j < 4; j++) {
                int nc = wn + j * 8 + gid;
                bf[j][0] = __float_as_uint(Bs[s][kk + tig    ][nc]);
                bf[j][1] = __float_as_uint(Bs[s][kk + tig + 4][nc]);
            }
            #pragma unroll
            for (int i = 0; i < 2; i++)
                #pragma unroll
                for (int j = 0; j < 4; j++) {
                    asm volatile(
                        "mma.sync.aligned.m16n8k8.row.col.f32.tf32.tf32.f32 "
                        "{%0,%1,%2,%3}, {%4,%5,%6,%7}, {%8,%9}, {%0,%1,%2,%3};"
                        : "+f"(acc[i][j][0]), "+f"(acc[i][j][1]),
                          "+f"(acc[i][j][2]), "+f"(acc[i][j][3])
                        : "r"(a[i][0]), "r"(a[i][1]), "r"(a[i][2]), "r"(a[i][3]),
                          "r"(bf[j][0]), "r"(bf[j][1]));
                }
        }

        if (more) {
            int d = s ^ 1;
            As[d][qA*4+0][mA] = f2tf32f(ra0.x);
            As[d][qA*4+1][mA] = f2tf32f(ra0.y);
            As[d][qA*4+2][mA] = f2tf32f(ra0.z);
            As[d][qA*4+3][mA] = f2tf32f(ra0.w);
            As[d][qA*4+4][mA] = f2tf32f(ra1.x);
            As[d][qA*4+5][mA] = f2tf32f(ra1.y);
            As[d][qA*4+6][mA] = f2tf32f(ra1.z);
            As[d][qA*4+7][mA] = f2tf32f(ra1.w);
            float4 c0 = make_float4(f2tf32f(rb0.x), f2tf32f(rb0.y), f2tf32f(rb0.z), f2tf32f(rb0.w));
            float4 c1 = make_float4(f2tf32f(rb1.x), f2tf32f(rb1.y), f2tf32f(rb1.z), f2tf32f(rb1.w));
            *(float4*)&Bs[d][kr][n4]     = c0;
            *(float4*)&Bs[d][kr + 8][n4] = c1;
        }
        __syncthreads();
    }

    // epilogue
    #pragma unroll
    for (int i = 0; i < 2; i++) {
        int r0 = o0 + wm + i * 16 + gid;   // row (o) for c0,c1
        int r1 = r0 + 8;                   // row for c2,c3
        float bv0 = 0.f, bv1 = 0.f;
        if (ksplit == 1) {
            if (bias)   { bv0 += bias[r0]; bv1 += bias[r1]; }
            if (biasBO) { bv0 += biasBO[b * O + r0]; bv1 += biasBO[b * O + r1]; }
        }
        size_t base0, base1;
        if (ksplit == 1) {
            base0 = (size_t)(b * O + r0) * N;
            base1 = (size_t)(b * O + r1) * N;
        } else {
            base0 = (size_t)(chunk * O + r0) * N;
            base1 = (size_t)(chunk * O + r1) * N;
        }
        #pragma unroll
        for (int j = 0; j < 4; j++) {
            int c = n0 + wn + j * 8 + 2 * tig;
            float2 v0 = make_float2(acc[i][j][0] + bv0, acc[i][j][1] + bv0);
            float2 v1 = make_float2(acc[i][j][2] + bv1, acc[i][j][3] + bv1);
            *(float2*)&Y[base0 + c] = v0;
            *(float2*)&Y[base1 + c] = v1;
        }
    }
}

// ---------------- BN training-mode statistics: scale/shift per channel ----------
__global__ void stats_kernel(const float* __restrict__ X, const float* __restrict__ g,
                             const float* __restrict__ be,
                             float* __restrict__ scale, float* __restrict__ shift, int C)
{
    int c = blockIdx.x;
    float s = 0.f, s2 = 0.f;
    for (int t = threadIdx.x; t < B_ * NPTS / 4; t += blockDim.x) {
        int b = t >> 10;
        int n4 = t & 1023;
        float4 v = *(const float4*)&X[((size_t)(b * C + c)) * NPTS + n4 * 4];
        s  += v.x + v.y + v.z + v.w;
        s2 += v.x * v.x + v.y * v.y + v.z * v.z + v.w * v.w;
    }
    __shared__ float sh1[256], sh2[256];
    sh1[threadIdx.x] = s; sh2[threadIdx.x] = s2;
    __syncthreads();
    for (int st = 128; st > 0; st >>= 1) {
        if (threadIdx.x < st) {
            sh1[threadIdx.x] += sh1[threadIdx.x + st];
            sh2[threadIdx.x] += sh2[threadIdx.x + st];
        }
        __syncthreads();
    }
    if (threadIdx.x == 0) {
        const float inv = 1.f / (float)(B_ * NPTS);
        float m  = sh1[0] * inv;
        float v  = sh2[0] * inv - m * m;
        float sc = g[c] / sqrtf(v + 1e-5f);
        scale[c] = sc;
        shift[c] = be[c] - m * sc;
    }
}

__global__ void apply_kernel(float* __restrict__ X, const float* __restrict__ scale,
                             const float* __restrict__ shift, int C, int relu)
{
    size_t i4 = ((size_t)blockIdx.x * blockDim.x + threadIdx.x) * 4;
    int c = (int)((i4 >> 12) % (size_t)C);
    float sc = scale[c], sf = shift[c];
    float4 v = *(float4*)&X[i4];
    v.x = v.x * sc + sf; v.y = v.y * sc + sf;
    v.z = v.z * sc + sf; v.w = v.w * sc + sf;
    if (relu) {
        v.x = fmaxf(v.x, 0.f); v.y = fmaxf(v.y, 0.f);
        v.z = fmaxf(v.z, 0.f); v.w = fmaxf(v.w, 0.f);
    }
    *(float4*)&X[i4] = v;
}

// ---------------- exact top-32 (desc, lower-index tie-break) per (b,c) row -------
__global__ void topk_kernel(const float* __restrict__ X, int* __restrict__ idx_out)
{
    int bc = blockIdx.x;                 // b*256 + c
    const float* row = X + (size_t)bc * NPTS;
    int tid = threadIdx.x;               // 256 threads

    float v[16];
    #pragma unroll
    for (int j = 0; j < 16; j++) v[j] = row[j * 256 + tid];

    __shared__ float swv[8];
    __shared__ int   swi[8];
    __shared__ int   sbi;

    for (int iter = 0; iter < 32; iter++) {
        float lv = -FLT_MAX; int li = 0x7fffffff;
        #pragma unroll
        for (int j = 0; j < 16; j++) {
            int n = j * 256 + tid;
            if (v[j] > lv || (v[j] == lv && n < li)) { lv = v[j]; li = n; }
        }
        #pragma unroll
        for (int off = 16; off > 0; off >>= 1) {
            float ov = __shfl_down_sync(0xffffffff, lv, off);
            int   oi = __shfl_down_sync(0xffffffff, li, off);
            if (ov > lv || (ov == lv && oi < li)) { lv = ov; li = oi; }
        }
        if ((tid & 31) == 0) { swv[tid >> 5] = lv; swi[tid >> 5] = li; }
        __syncthreads();
        if (tid == 0) {
            float gv = swv[0]; int gi = swi[0];
            #pragma unroll
            for (int w = 1; w < 8; w++)
                if (swv[w] > gv || (swv[w] == gv && swi[w] < gi)) { gv = swv[w]; gi = swi[w]; }
            sbi = gi;
            idx_out[bc * 32 + iter] = gi;
        }
        __syncthreads();
        int gi = sbi;
        if ((gi & 255) == tid) v[gi >> 8] = -FLT_MAX;
        __syncthreads();
    }
}

// ---------------- softpool gather: G[(c*256+w)*512 + b*32+h] = h3[b,c,idx[b,w,h]] --
__global__ void gather_kernel(const float* __restrict__ h3, const int* __restrict__ idx,
                              float* __restrict__ G)
{
    size_t i = (size_t)blockIdx.x * blockDim.x + threadIdx.x;   // 65536*512 total
    int col = (int)(i & 511);
    size_t k = i >> 9;
    int b = col >> 5, h = col & 31;
    int c = (int)(k >> 8), w = (int)(k & 255);
    int n = idx[((b << 8) + w) * 32 + h];
    G[i] = h3[(((size_t)(b * 256 + c)) << 12) + n];
}

// ---------------- conv8 split-K reduce -------------------------------------------
__global__ void reduce8_kernel(const float* __restrict__ P, const float* __restrict__ b8,
                               float* __restrict__ y8)
{
    int i = blockIdx.x * blockDim.x + threadIdx.x;   // 256*512
    float s = b8[i >> 9];
    #pragma unroll
    for (int ch = 0; ch < 16; ch++) s += P[(size_t)ch * 131072 + i];
    y8[i] = s;
}

// ---------------- conv9: y9[b,o] = b9[o] + sum_{c,h} y8[c, b*32+h]*w9[o,c,h] ------
__global__ void conv9_kernel(const float* __restrict__ y8, const float* __restrict__ w9,
                             const float* __restrict__ b9, float* __restrict__ y9)
{
    int b = blockIdx.x >> 8;
    int o = blockIdx.x & 255;
    int c = threadIdx.x;    // 256
    float s = 0.f;
    const float* yb = y8 + (size_t)c * 512 + b * 32;
    const float* wr = w9 + ((size_t)o * 256 + c) * 32;
    #pragma unroll
    for (int h = 0; h < 32; h++) s += yb[h] * wr[h];
    __shared__ float sh[256];
    sh[c] = s; __syncthreads();
    for (int st = 128; st > 0; st >>= 1) {
        if (c < st) sh[c] += sh[c + st];
        __syncthreads();
    }
    if (c == 0) y9[b * 256 + o] = sh[0] + b9[o];
}

// ---------------- glob contribution to conv4: gcon[b,o] = sum_c w4[o,c]*y9[b,c] ---
__global__ void gcon_kernel(const float* __restrict__ w4, const float* __restrict__ y9,
                            float* __restrict__ gcon)
{
    int i = blockIdx.x * blockDim.x + threadIdx.x;   // 16*512
    int b = i >> 9, o = i & 511;
    float s = 0.f;
    for (int c = 0; c < 256; c++) s += w4[o * 320 + c] * y9[b * 256 + c];
    gcon[i] = s;
}

// ---------------- conv7 + tanh ----------------------------------------------------
__global__ void conv7_kernel(const float* __restrict__ h6, const float* __restrict__ w7,
                             const float* __restrict__ b7, float* __restrict__ out)
{
    int i = blockIdx.x * blockDim.x + threadIdx.x;   // B*NPTS
    int b = i >> 12, n = i & (NPTS - 1);
    float s0 = b7[0], s1 = b7[1], s2 = b7[2];
    const float* hb = h6 + (((size_t)b * 128) << 12) + n;
    for (int c = 0; c < 128; c++) {
        float v = hb[(size_t)c * NPTS];
        s0 += w7[c] * v;
        s1 += w7[128 + c] * v;
        s2 += w7[256 + c] * v;
    }
    out[((size_t)(b * 3 + 0)) * NPTS + n] = tanhf(s0);
    out[((size_t)(b * 3 + 1)) * NPTS + n] = tanhf(s1);
    out[((size_t)(b * 3 + 2)) * NPTS + n] = tanhf(s2);
}

// ===================================================================================
extern "C" void kernel_launch(void* const* d_in, const int* in_sizes, int n_in,
                              void* d_out, int out_size)
{
    const float* x   = (const float*)d_in[0];
    const float* w1  = (const float*)d_in[1];
    const float* b1  = (const float*)d_in[2];
    const float* g1  = (const float*)d_in[3];
    const float* be1 = (const float*)d_in[4];
    const float* w2  = (const float*)d_in[5];
    const float* b2  = (const float*)d_in[6];
    const float* g2  = (const float*)d_in[7];
    const float* be2 = (const float*)d_in[8];
    const float* w3  = (const float*)d_in[9];
    const float* b3  = (const float*)d_in[10];
    const float* g3  = (const float*)d_in[11];
    const float* be3 = (const float*)d_in[12];
    const float* w4  = (const float*)d_in[13];
    const float* b4  = (const float*)d_in[14];
    const float* g4  = (const float*)d_in[15];
    const float* be4 = (const float*)d_in[16];
    const float* w5  = (const float*)d_in[17];
    const float* b5  = (const float*)d_in[18];
    const float* g5  = (const float*)d_in[19];
    const float* be5 = (const float*)d_in[20];
    const float* w6  = (const float*)d_in[21];
    const float* b6  = (const float*)d_in[22];
    const float* g6  = (const float*)d_in[23];
    const float* be6 = (const float*)d_in[24];
    const float* w7  = (const float*)d_in[25];
    const float* b7  = (const float*)d_in[26];
    const float* w8  = (const float*)d_in[27];
    const float* b8  = (const float*)d_in[28];
    const float* w9  = (const float*)d_in[29];
    const float* b9  = (const float*)d_in[30];
    float* out = (float*)d_out;

    float *h1, *h2, *h3, *h4, *h5, *h6, *G, *P8, *y8, *y9, *gcon, *scale, *shift;
    int* idxp;
    cudaGetSymbolAddress((void**)&h1,    g_h1);
    cudaGetSymbolAddress((void**)&h2,    g_h2);
    cudaGetSymbolAddress((void**)&h3,    g_h3);
    cudaGetSymbolAddress((void**)&h4,    g_h4);
    cudaGetSymbolAddress((void**)&h5,    g_h5);
    cudaGetSymbolAddress((void**)&h6,    g_h6);
    cudaGetSymbolAddress((void**)&G,     g_G);
    cudaGetSymbolAddress((void**)&P8,    g_P8);
    cudaGetSymbolAddress((void**)&y8,    g_y8);
    cudaGetSymbolAddress((void**)&y9,    g_y9);
    cudaGetSymbolAddress((void**)&gcon,  g_gcon);
    cudaGetSymbolAddress((void**)&idxp,  g_idx);
    cudaGetSymbolAddress((void**)&scale, g_scale);
    cudaGetSymbolAddress((void**)&shift, g_shift);

    const int NB = NPTS / 64;   // 64 tile-columns over points

    // conv1 (4->64) + BN + relu   — exact fp32 (feeds top-k path)
    gemm_kernel<<<dim3(NB, 1, B_), 256>>>(x, w1, b1, nullptr, h1, 64, 4, NPTS, 4, 1);
    stats_kernel<<<64, 256>>>(h1, g1, be1, scale, shift, 64);
    apply_kernel<<<(B_ * 64 * NPTS) / 1024, 256>>>(h1, scale, shift, 64, 1);

    // conv2 (64->128) + BN + relu — exact fp32
    gemm_kernel<<<dim3(NB, 2, B_), 256>>>(h1, w2, b2, nullptr, h2, 128, 64, NPTS, 64, 1);
    stats_kernel<<<128, 256>>>(h2, g2, be2, scale, shift, 128);
    apply_kernel<<<(B_ * 128 * NPTS) / 1024, 256>>>(h2, scale, shift, 128, 1);

    // conv3 (128->256) + BN (no relu) — exact fp32 (top-k input)
    gemm_kernel<<<dim3(NB, 4, B_), 256>>>(h2, w3, b3, nullptr, h3, 256, 128, NPTS, 128, 1);
    stats_kernel<<<256, 256>>>(h3, g3, be3, scale, shift, 256);
    apply_kernel<<<(B_ * 256 * NPTS) / 1024, 256>>>(h3, scale, shift, 256, 0);

    // top-32 per (b, sort channel), then gather softpool matrix
    topk_kernel<<<B_ * 256, 256>>>(h3, idxp);
    gather_kernel<<<(int)(((size_t)65536 * 512) / 256), 256>>>(h3, idxp, G);

    // conv8 (tf32 tensor cores, split-K 16)
    gemm_tf32<<<dim3(512 / 64, 256 / 64, 16), 128>>>(G, w8, nullptr, nullptr, P8,
                                                     256, 65536, 512, 65536, 16);
    reduce8_kernel<<<(256 * 512) / 256, 256>>>(P8, b8, y8);

    // conv9 -> global feature y9[b,o]
    conv9_kernel<<<B_ * 256, 256>>>(y8, w9, b9, y9);

    // fold glob part of conv4 into per-(b,o) bias
    gcon_kernel<<<(B_ * 512) / 256, 256>>>(w4, y9, gcon);

    // conv4 (pointfeat 64 -> 512, + gcon + b4) + BN + relu  (tf32)
    gemm_tf32<<<dim3(NB, 8, B_), 128>>>(h1, w4 + 256, b4, gcon, h4, 512, 64, NPTS, 320, 1);
    stats_kernel<<<512, 256>>>(h4, g4, be4, scale, shift, 512);
    apply_kernel<<<(B_ * 512 * NPTS) / 1024, 256>>>(h4, scale, shift, 512, 1);

    // conv5 (512->256) + BN + relu  (tf32)
    gemm_tf32<<<dim3(NB, 4, B_), 128>>>(h4, w5, b5, nullptr, h5, 256, 512, NPTS, 512, 1);
    stats_kernel<<<256, 256>>>(h5, g5, be5, scale, shift, 256);
    apply_kernel<<<(B_ * 256 * NPTS) / 1024, 256>>>(h5, scale, shift, 256, 1);

    // conv6 (256->128) + BN + relu  (tf32)
    gemm_tf32<<<dim3(NB, 2, B_), 128>>>(h5, w6, b6, nullptr, h6, 128, 256, NPTS, 256, 1);
    stats_kernel<<<128, 256>>>(h6, g6, be6, scale, shift, 128);
    apply_kernel<<<(B_ * 128 * NPTS) / 1024, 256>>>(h6, scale, shift, 128, 1);

    // conv7 (128->3) + tanh
    conv7_kernel<<<(B_ * NPTS) / 256, 256>>>(h6, w7, b7, out);
}

// round 3
// speedup vs baseline: 1.6708x; 1.1718x over previous
#include <cuda_runtime.h>
#include <math.h>
#include <float.h>
#include <stdint.h>

#define B_    16
#define NPTS  4096

// ---------------- scratch (static device globals) ---------------------------------
__device__ float g_h1[(size_t)B_ * 64  * NPTS];
__device__ float g_h2[(size_t)B_ * 128 * NPTS];
__device__ float g_h3[(size_t)B_ * 256 * NPTS];
__device__ float g_h3t[(size_t)B_ * NPTS * 256];   // [b][n][c]
__device__ float g_h4[(size_t)B_ * 512 * NPTS];
__device__ float g_h5[(size_t)B_ * 256 * NPTS];
__device__ float g_h6[(size_t)B_ * 128 * NPTS];
__device__ float g_w8t[(size_t)256 * 256 * 256];   // [w][c][o]
__device__ float g_P8[(size_t)16 * 256 * 512];     // split-K partials for conv8
__device__ float g_y8[256 * 512];                  // conv8 out, [o][b*32+h]
__device__ float g_y9[B_ * 512];
__device__ float g_gcon[B_ * 512];
__device__ int   g_idx[B_ * 256 * 32];
__device__ float g_scale[6 * 512];
__device__ float g_shift[6 * 512];

__device__ __forceinline__ float f2tf32f(float f) {
    uint32_t u;
    asm("cvt.rna.tf32.f32 %0, %1;" : "=r"(u) : "f"(f));
    return __uint_as_float(u);
}

__device__ __forceinline__ void mma_tf32(float* d, const uint32_t* a, const uint32_t* b) {
    asm volatile(
        "mma.sync.aligned.m16n8k8.row.col.f32.tf32.tf32.f32 "
        "{%0,%1,%2,%3}, {%4,%5,%6,%7}, {%8,%9}, {%0,%1,%2,%3};"
        : "+f"(d[0]), "+f"(d[1]), "+f"(d[2]), "+f"(d[3])
        : "r"(a[0]), "r"(a[1]), "r"(a[2]), "r"(a[3]), "r"(b[0]), "r"(b[1]));
}

// ---------------- fp32 SGEMM (exact; conv1-3 which feed top-k), BN fused on load ---
__global__ void gemm_f32(const float* __restrict__ X, const float* __restrict__ W,
                         const float* __restrict__ bias, float* __restrict__ Y,
                         int O, int K, int N, int ldw,
                         const float* __restrict__ bnS, const float* __restrict__ bnF,
                         int relu)
{
    __shared__ float As[16][66];
    __shared__ float Bs[16][64];

    int b  = blockIdx.z;
    int o0 = blockIdx.y * 64;
    int n0 = blockIdx.x * 64;
    const float* Xb = X + (size_t)b * K * N;

    int tid = threadIdx.x;
    int tm  = tid >> 4;
    int tn  = tid & 15;

    float acc[4][4] = {};

    for (int k0 = 0; k0 < K; k0 += 16) {
        #pragma unroll
        for (int i = 0; i < 4; i++) {
            int e = tid + i * 256;
            int m = e >> 4, k = e & 15;
            As[k][m] = (k0 + k < K) ? W[(size_t)(o0 + m) * ldw + k0 + k] : 0.f;
        }
        #pragma unroll
        for (int i = 0; i < 4; i++) {
            int e = tid + i * 256;
            int k = e >> 6, n = e & 63;
            float v = 0.f;
            if (k0 + k < K) {
                v = Xb[(size_t)(k0 + k) * N + n0 + n];
                if (bnS) {
                    v = v * bnS[k0 + k] + bnF[k0 + k];
                    if (relu) v = fmaxf(v, 0.f);
                }
            }
            Bs[k][n] = v;
        }
        __syncthreads();
        #pragma unroll
        for (int kk = 0; kk < 16; kk++) {
            float a[4], bb[4];
            #pragma unroll
            for (int i = 0; i < 4; i++) a[i]  = As[kk][tm * 4 + i];
            #pragma unroll
            for (int j = 0; j < 4; j++) bb[j] = Bs[kk][tn * 4 + j];
            #pragma unroll
            for (int i = 0; i < 4; i++)
                #pragma unroll
                for (int j = 0; j < 4; j++)
                    acc[i][j] += a[i] * bb[j];
        }
        __syncthreads();
    }

    #pragma unroll
    for (int i = 0; i < 4; i++) {
        int o = o0 + tm * 4 + i;
        float bv = bias ? bias[o] : 0.f;
        size_t base = (size_t)(b * O + o) * N;
        #pragma unroll
        for (int j = 0; j < 4; j++)
            Y[base + n0 + tn * 4 + j] = acc[i][j] + bv;
    }
}

// ---------------- tf32 tensor-core GEMM, 128x64 tile, 256 thr, BN fused on B load --
__global__ void __launch_bounds__(256) gemm_tf32(
    const float* __restrict__ X, const float* __restrict__ W,
    const float* __restrict__ bias, const float* __restrict__ biasBO,
    float* __restrict__ Y, int O, int K, int N, int ldw,
    const float* __restrict__ bnS, const float* __restrict__ bnF, int relu)
{
    __shared__ float As[2][16][136];   // [k][m], stride 136 ≡ 8 (mod 32) banks
    __shared__ float Bs[2][16][72];    // [k][n]

    int b  = blockIdx.z;
    int o0 = blockIdx.y * 128;
    int n0 = blockIdx.x * 64;
    const float* Xb = X + (size_t)b * K * N;

    int tid  = threadIdx.x;
    int lane = tid & 31;
    int warp = tid >> 5;
    int wm   = (warp & 3) * 32;
    int wn   = (warp >> 2) * 32;
    int gid  = lane >> 2;
    int tig  = lane & 3;

    int mA = tid & 127;
    int qA = (tid >> 7) * 2;            // quads qA, qA+1
    const float* wp = W + (size_t)(o0 + mA) * ldw;
    int kr = tid >> 4;                  // 0..15
    int n4 = (tid & 15) * 4;

    float acc[2][4][4] = {};
    float4 ra0, ra1, rb;

    // prologue (k0 = 0)
    {
        ra0 = *(const float4*)(wp + qA * 4);
        ra1 = *(const float4*)(wp + qA * 4 + 4);
        rb  = *(const float4*)(Xb + (size_t)kr * N + n0 + n4);
        if (bnS) {
            float sc = bnS[kr], sf = bnF[kr];
            rb.x = rb.x * sc + sf; rb.y = rb.y * sc + sf;
            rb.z = rb.z * sc + sf; rb.w = rb.w * sc + sf;
            if (relu) {
                rb.x = fmaxf(rb.x, 0.f); rb.y = fmaxf(rb.y, 0.f);
                rb.z = fmaxf(rb.z, 0.f); rb.w = fmaxf(rb.w, 0.f);
            }
        }
        As[0][qA*4+0][mA] = f2tf32f(ra0.x);
        As[0][qA*4+1][mA] = f2tf32f(ra0.y);
        As[0][qA*4+2][mA] = f2tf32f(ra0.z);
        As[0][qA*4+3][mA] = f2tf32f(ra0.w);
        As[0][qA*4+4][mA] = f2tf32f(ra1.x);
        As[0][qA*4+5][mA] = f2tf32f(ra1.y);
        As[0][qA*4+6][mA] = f2tf32f(ra1.z);
        As[0][qA*4+7][mA] = f2tf32f(ra1.w);
        float4 c = make_float4(f2tf32f(rb.x), f2tf32f(rb.y), f2tf32f(rb.z), f2tf32f(rb.w));
        *(float4*)&Bs[0][kr][n4] = c;
    }
    __syncthreads();

    int nIter = K / 16;
    for (int it = 0; it < nIter; it++) {
        int s = it & 1;
        bool more = (it + 1 < nIter);
        if (more) {
            int k0 = (it + 1) * 16;
            ra0 = *(const float4*)(wp + k0 + qA * 4);
            ra1 = *(const float4*)(wp + k0 + qA * 4 + 4);
            rb  = *(const float4*)(Xb + (size_t)(k0 + kr) * N + n0 + n4);
            if (bnS) {
                float sc = bnS[k0 + kr], sf = bnF[k0 + kr];
                rb.x = rb.x * sc + sf; rb.y = rb.y * sc + sf;
                rb.z = rb.z * sc + sf; rb.w = rb.w * sc + sf;
                if (relu) {
                    rb.x = fmaxf(rb.x, 0.f); rb.y = fmaxf(rb.y, 0.f);
                    rb.z = fmaxf(rb.z, 0.f); rb.w = fmaxf(rb.w, 0.f);
                }
            }
        }

        #pragma unroll
        for (int ks = 0; ks < 2; ks++) {
            int kk = ks * 8;
            uint32_t a[2][4], bf[4][2];
            #pragma unroll
            for (int i = 0; i < 2; i++) {
                int mr = wm + i * 16 + gid;
                a[i][0] = __float_as_uint(As[s][kk + tig    ][mr    ]);
                a[i][1] = __float_as_uint(As[s][kk + tig    ][mr + 8]);
                a[i][2] = __float_as_uint(As[s][kk + tig + 4][mr    ]);
                a[i][3] = __float_as_uint(As[s][kk + tig + 4][mr + 8]);
            }
            #pragma unroll
            for (int j = 0; j < 4; j++) {
                int nc = wn + j * 8 + gid;
                bf[j][0] = __float_as_uint(Bs[s][kk + tig    ][nc]);
                bf[j][1] = __float_as_uint(Bs[s][kk + tig + 4][nc]);
            }
            #pragma unroll
            for (int i = 0; i < 2; i++)
                #pragma unroll
                for (int j = 0; j < 4; j++)
                    mma_tf32(acc[i][j], a[i], bf[j]);
        }

        if (more) {
            int d = s ^ 1;
            As[d][qA*4+0][mA] = f2tf32f(ra0.x);
            As[d][qA*4+1][mA] = f2tf32f(ra0.y);
            As[d][qA*4+2][mA] = f2tf32f(ra0.z);
            As[d][qA*4+3][mA] = f2tf32f(ra0.w);
            As[d][qA*4+4][mA] = f2tf32f(ra1.x);
            As[d][qA*4+5][mA] = f2tf32f(ra1.y);
            As[d][qA*4+6][mA] = f2tf32f(ra1.z);
            As[d][qA*4+7][mA] = f2tf32f(ra1.w);
            float4 c = make_float4(f2tf32f(rb.x), f2tf32f(rb.y), f2tf32f(rb.z), f2tf32f(rb.w));
            *(float4*)&Bs[d][kr][n4] = c;
        }
        __syncthreads();
    }

    #pragma unroll
    for (int i = 0; i < 2; i++) {
        int r0 = o0 + wm + i * 16 + gid;
        int r1 = r0 + 8;
        float bv0 = 0.f, bv1 = 0.f;
        if (bias)   { bv0 += bias[r0]; bv1 += bias[r1]; }
        if (biasBO) { bv0 += biasBO[b * O + r0]; bv1 += biasBO[b * O + r1]; }
        size_t base0 = (size_t)(b * O + r0) * N;
        size_t base1 = (size_t)(b * O + r1) * N;
        #pragma unroll
        for (int j = 0; j < 4; j++) {
            int c = n0 + wn + j * 8 + 2 * tig;
            *(float2*)&Y[base0 + c] = make_float2(acc[i][j][0] + bv0, acc[i][j][1] + bv0);
            *(float2*)&Y[base1 + c] = make_float2(acc[i][j][2] + bv1, acc[i][j][3] + bv1);
        }
    }
}

// ---------------- conv8 fused gather GEMM ------------------------------------------
// P8[chunk][o][col] = sum_{k in chunk} w8tt[k][o] * (h3t[b][n(b,w,h)][c]*sc3[c]+sf3[c])
// k = w*256 + c; chunk covers w in [chunk*16, chunk*16+16). BM=256 (all o), BN=64.
__global__ void __launch_bounds__(256) conv8_kernel(
    const float* __restrict__ h3t, const float* __restrict__ w8tt,
    const int* __restrict__ idx, const float* __restrict__ sc3,
    const float* __restrict__ sf3, float* __restrict__ P8)
{
    __shared__ float As[2][16][264];
    __shared__ float Bs[2][16][72];
    __shared__ int   sIdx[1024];

    int col0  = blockIdx.x * 64;
    int chunk = blockIdx.y;
    int tid = threadIdx.x;
    int lane = tid & 31, warp = tid >> 5;
    int wm = warp * 32;
    int gid = lane >> 2, tig = lane & 3;

    #pragma unroll
    for (int i = 0; i < 4; i++) {
        int e = tid + i * 256;
        int w16 = e >> 6, j = e & 63;
        int col = col0 + j, b = col >> 5, h = col & 31;
        sIdx[e] = idx[(((b << 8) + (chunk * 16 + w16)) << 5) + h];
    }
    __syncthreads();

    // B gather setup: thread handles col0+jB, c-quad cq
    int jB = tid >> 2, cq = tid & 3;
    const float* h3b = h3t + ((size_t)((col0 + jB) >> 5) << 20);

    // A setup: tile 16(k) x 256(o); thread: row kA, o range oA..oA+15
    int kA = tid >> 4;
    int oA = (tid & 15) * 16;
    const float* abase = w8tt + (size_t)chunk * 4096 * 256;

    float acc[2][8][4] = {};
    float4 a0, a1, a2, a3, bv, scv, sfv;

    // prefetch stage 0  (w16=0, c0=0)
    {
        const float* ap = abase + (size_t)kA * 256 + oA;
        a0 = *(const float4*)(ap);
        a1 = *(const float4*)(ap + 4);
        a2 = *(const float4*)(ap + 8);
        a3 = *(const float4*)(ap + 12);
        int n = sIdx[jB];
        bv  = *(const float4*)(h3b + ((size_t)n << 8) + cq * 4);
        scv = *(const float4*)(sc3 + cq * 4);
        sfv = *(const float4*)(sf3 + cq * 4);
    }
    // store stage 0
    {
        float* ar = &As[0][kA][oA];
        *(float4*)(ar)      = make_float4(f2tf32f(a0.x), f2tf32f(a0.y), f2tf32f(a0.z), f2tf32f(a0.w));
        *(float4*)(ar + 4)  = make_float4(f2tf32f(a1.x), f2tf32f(a1.y), f2tf32f(a1.z), f2tf32f(a1.w));
        *(float4*)(ar + 8)  = make_float4(f2tf32f(a2.x), f2tf32f(a2.y), f2tf32f(a2.z), f2tf32f(a2.w));
        *(float4*)(ar + 12) = make_float4(f2tf32f(a3.x), f2tf32f(a3.y), f2tf32f(a3.z), f2tf32f(a3.w));
        Bs[0][cq*4+0][jB] = f2tf32f(bv.x * scv.x + sfv.x);
        Bs[0][cq*4+1][jB] = f2tf32f(bv.y * scv.y + sfv.y);
        Bs[0][cq*4+2][jB] = f2tf32f(bv.z * scv.z + sfv.z);
        Bs[0][cq*4+3][jB] = f2tf32f(bv.w * scv.w + sfv.w);
    }
    __syncthreads();

    for (int t = 0; t < 256; t++) {
        int s = t & 1;
        bool more = (t < 255);
        if (more) {
            int t1 = t + 1;
            int w16 = t1 >> 4, c0 = (t1 & 15) * 16;
            const float* ap = abase + (size_t)(w16 * 256 + c0 + kA) * 256 + oA;
            a0 = *(const float4*)(ap);
            a1 = *(const float4*)(ap + 4);
            a2 = *(const float4*)(ap + 8);
            a3 = *(const float4*)(ap + 12);
            int n = sIdx[w16 * 64 + jB];
            bv  = *(const float4*)(h3b + ((size_t)n << 8) + c0 + cq * 4);
            scv = *(const float4*)(sc3 + c0 + cq * 4);
            sfv = *(const float4*)(sf3 + c0 + cq * 4);
        }

        #pragma unroll
        for (int ks = 0; ks < 2; ks++) {
            int kk = ks * 8;
            uint32_t a[2][4], bf[8][2];
            #pragma unroll
            for (int i = 0; i < 2; i++) {
                int mr = wm + i * 16 + gid;
                a[i][0] = __float_as_uint(As[s][kk + tig    ][mr    ]);
                a[i][1] = __float_as_uint(As[s][kk + tig    ][mr + 8]);
                a[i][2] = __float_as_uint(As[s][kk + tig + 4][mr    ]);
                a[i][3] = __float_as_uint(As[s][kk + tig + 4][mr + 8]);
            }
            #pragma unroll
            for (int j = 0; j < 8; j++) {
                int nc = j * 8 + gid;
                bf[j][0] = __float_as_uint(Bs[s][kk + tig    ][nc]);
                bf[j][1] = __float_as_uint(Bs[s][kk + tig + 4][nc]);
            }
            #pragma unroll
            for (int i = 0; i < 2; i++)
                #pragma unroll
                for (int j = 0; j < 8; j++)
                    mma_tf32(acc[i][j], a[i], bf[j]);
        }

        if (more) {
            int d = s ^ 1;
            float* ar = &As[d][kA][oA];
            *(float4*)(ar)      = make_float4(f2tf32f(a0.x), f2tf32f(a0.y), f2tf32f(a0.z), f2tf32f(a0.w));
            *(float4*)(ar + 4)  = make_float4(f2tf32f(a1.x), f2tf32f(a1.y), f2tf32f(a1.z), f2tf32f(a1.w));
            *(float4*)(ar + 8)  = make_float4(f2tf32f(a2.x), f2tf32f(a2.y), f2tf32f(a2.z), f2tf32f(a2.w));
            *(float4*)(ar + 12) = make_float4(f2tf32f(a3.x), f2tf32f(a3.y), f2tf32f(a3.z), f2tf32f(a3.w));
            Bs[d][cq*4+0][jB] = f2tf32f(bv.x * scv.x + sfv.x);
            Bs[d][cq*4+1][jB] = f2tf32f(bv.y * scv.y + sfv.y);
            Bs[d][cq*4+2][jB] = f2tf32f(bv.z * scv.z + sfv.z);
            Bs[d][cq*4+3][jB] = f2tf32f(bv.w * scv.w + sfv.w);
        }
        __syncthreads();
    }

    #pragma unroll
    for (int i = 0; i < 2; i++) {
        int r0 = wm + i * 16 + gid;
        size_t base0 = ((size_t)chunk * 256 + r0) * 512 + col0;
        size_t base1 = ((size_t)chunk * 256 + r0 + 8) * 512 + col0;
        #pragma unroll
        for (int j = 0; j < 8; j++) {
            int c = j * 8 + 2 * tig;
            *(float2*)&P8[base0 + c] = make_float2(acc[i][j][0], acc[i][j][1]);
            *(float2*)&P8[base1 + c] = make_float2(acc[i][j][2], acc[i][j][3]);
        }
    }
}

// ---------------- transposes -------------------------------------------------------
// h3 [b][c][n] -> h3t [b][n][c]
__global__ void transpose_h3(const float* __restrict__ src, float* __restrict__ dst)
{
    __shared__ float s[32][33];
    int b = blockIdx.z, n0 = blockIdx.x * 32, c0 = blockIdx.y * 32;
    int tx = threadIdx.x, ty = threadIdx.y;
    const float* sb = src + ((size_t)b << 20);
    float* db = dst + ((size_t)b << 20);
    #pragma unroll
    for (int k = 0; k < 4; k++)
        s[ty + 8 * k][tx] = sb[(size_t)(c0 + ty + 8 * k) * 4096 + n0 + tx];
    __syncthreads();
    #pragma unroll
    for (int k = 0; k < 4; k++)
        db[(size_t)(n0 + ty + 8 * k) * 256 + c0 + tx] = s[tx][ty + 8 * k];
}

// w8 [o][c][w] -> w8tt [w][c][o]
__global__ void transpose_w8(const float* __restrict__ src, float* __restrict__ dst)
{
    __shared__ float s[32][33];
    int c = blockIdx.z, o0 = blockIdx.y * 32, w0 = blockIdx.x * 32;
    int tx = threadIdx.x, ty = threadIdx.y;
    #pragma unroll
    for (int k = 0; k < 4; k++)
        s[ty + 8 * k][tx] = src[(size_t)(o0 + ty + 8 * k) * 65536 + c * 256 + w0 + tx];
    __syncthreads();
    #pragma unroll
    for (int k = 0; k < 4; k++)
        dst[(size_t)(w0 + ty + 8 * k) * 65536 + c * 256 + o0 + tx] = s[tx][ty + 8 * k];
}

// ---------------- BN statistics ----------------------------------------------------
__global__ void stats_kernel(const float* __restrict__ X, const float* __restrict__ g,
                             const float* __restrict__ be,
                             float* __restrict__ scale, float* __restrict__ shift, int C)
{
    int c = blockIdx.x;
    float s = 0.f, s2 = 0.f;
    for (int t = threadIdx.x; t < B_ * NPTS / 4; t += blockDim.x) {
        int b = t >> 10;
        int n4 = t & 1023;
        float4 v = *(const float4*)&X[((size_t)(b * C + c)) * NPTS + n4 * 4];
        s  += v.x + v.y + v.z + v.w;
        s2 += v.x * v.x + v.y * v.y + v.z * v.z + v.w * v.w;
    }
    __shared__ float sh1[256], sh2[256];
    sh1[threadIdx.x] = s; sh2[threadIdx.x] = s2;
    __syncthreads();
    for (int st = 128; st > 0; st >>= 1) {
        if (threadIdx.x < st) {
            sh1[threadIdx.x] += sh1[threadIdx.x + st];
            sh2[threadIdx.x] += sh2[threadIdx.x + st];
        }
        __syncthreads();
    }
    if (threadIdx.x == 0) {
        const float inv = 1.f / (float)(B_ * NPTS);
        float m  = sh1[0] * inv;
        float v  = sh2[0] * inv - m * m;
        float sc = g[c] / sqrtf(v + 1e-5f);
        scale[c] = sc;
        shift[c] = be[c] - m * sc;
    }
}

// ---------------- exact top-32 per (b,c) row (raw h3; scale>0 preserves order) ----
__global__ void topk_kernel(const float* __restrict__ X, int* __restrict__ idx_out)
{
    int bc = blockIdx.x;
    const float* row = X + (size_t)bc * NPTS;
    int tid = threadIdx.x;

    float v[16];
    #pragma unroll
    for (int j = 0; j < 16; j++) v[j] = row[j * 256 + tid];

    __shared__ float swv[8];
    __shared__ int   swi[8];
    __shared__ int   sbi;

    for (int iter = 0; iter < 32; iter++) {
        float lv = -FLT_MAX; int li = 0x7fffffff;
        #pragma unroll
        for (int j = 0; j < 16; j++) {
            int n = j * 256 + tid;
            if (v[j] > lv || (v[j] == lv && n < li)) { lv = v[j]; li = n; }
        }
        #pragma unroll
        for (int off = 16; off > 0; off >>= 1) {
            float ov = __shfl_down_sync(0xffffffff, lv, off);
            int   oi = __shfl_down_sync(0xffffffff, li, off);
            if (ov > lv || (ov == lv && oi < li)) { lv = ov; li = oi; }
        }
        if ((tid & 31) == 0) { swv[tid >> 5] = lv; swi[tid >> 5] = li; }
        __syncthreads();
        if (tid == 0) {
            float gv = swv[0]; int gi = swi[0];
            #pragma unroll
            for (int w = 1; w < 8; w++)
                if (swv[w] > gv || (swv[w] == gv && swi[w] < gi)) { gv = swv[w]; gi = swi[w]; }
            sbi = gi;
            idx_out[bc * 32 + iter] = gi;
        }
        __syncthreads();
        int gi = sbi;
        if ((gi & 255) == tid) v[gi >> 8] = -FLT_MAX;
        __syncthreads();
    }
}

// ---------------- conv8 split-K reduce ---------------------------------------------
__global__ void reduce8_kernel(const float* __restrict__ P, const float* __restrict__ b8,
                               float* __restrict__ y8)
{
    int i = blockIdx.x * blockDim.x + threadIdx.x;
    float s = b8[i >> 9];
    #pragma unroll
    for (int ch = 0; ch < 16; ch++) s += P[(size_t)ch * 131072 + i];
    y8[i] = s;
}

// ---------------- conv9 ------------------------------------------------------------
__global__ void conv9_kernel(const float* __restrict__ y8, const float* __restrict__ w9,
                             const float* __restrict__ b9, float* __restrict__ y9)
{
    int b = blockIdx.x >> 8;
    int o = blockIdx.x & 255;
    int c = threadIdx.x;
    float s = 0.f;
    const float* yb = y8 + (size_t)c * 512 + b * 32;
    const float* wr = w9 + ((size_t)o * 256 + c) * 32;
    #pragma unroll
    for (int h = 0; h < 32; h++) s += yb[h] * wr[h];
    __shared__ float sh[256];
    sh[c] = s; __syncthreads();
    for (int st = 128; st > 0; st >>= 1) {
        if (c < st) sh[c] += sh[c + st];
        __syncthreads();
    }
    if (c == 0) y9[b * 256 + o] = sh[0] + b9[o];
}

// ---------------- glob contribution to conv4 ---------------------------------------
__global__ void gcon_kernel(const float* __restrict__ w4, const float* __restrict__ y9,
                            float* __restrict__ gcon)
{
    int i = blockIdx.x * blockDim.x + threadIdx.x;
    int b = i >> 9, o = i & 511;
    float s = 0.f;
    for (int c = 0; c < 256; c++) s += w4[o * 320 + c] * y9[b * 256 + c];
    gcon[i] = s;
}

// ---------------- conv7 + bn6 + relu + tanh ----------------------------------------
__global__ void conv7_kernel(const float* __restrict__ h6, const float* __restrict__ sc,
                             const float* __restrict__ sf, const float* __restrict__ w7,
                             const float* __restrict__ b7, float* __restrict__ out)
{
    int i = blockIdx.x * blockDim.x + threadIdx.x;
    int b = i >> 12, n = i & (NPTS - 1);
    float s0 = b7[0], s1 = b7[1], s2 = b7[2];
    const float* hb = h6 + (((size_t)b * 128) << 12) + n;
    for (int c = 0; c < 128; c++) {
        float v = fmaxf(hb[(size_t)c * NPTS] * sc[c] + sf[c], 0.f);
        s0 += w7[c] * v;
        s1 += w7[128 + c] * v;
        s2 += w7[256 + c] * v;
    }
    out[((size_t)(b * 3 + 0)) * NPTS + n] = tanhf(s0);
    out[((size_t)(b * 3 + 1)) * NPTS + n] = tanhf(s1);
    out[((size_t)(b * 3 + 2)) * NPTS + n] = tanhf(s2);
}

// ===================================================================================
extern "C" void kernel_launch(void* const* d_in, const int* in_sizes, int n_in,
                              void* d_out, int out_size)
{
    const float* x   = (const float*)d_in[0];
    const float* w1  = (const float*)d_in[1];
    const float* b1  = (const float*)d_in[2];
    const float* g1  = (const float*)d_in[3];
    const float* be1 = (const float*)d_in[4];
    const float* w2  = (const float*)d_in[5];
    const float* b2  = (const float*)d_in[6];
    const float* g2  = (const float*)d_in[7];
    const float* be2 = (const float*)d_in[8];
    const float* w3  = (const float*)d_in[9];
    const float* b3  = (const float*)d_in[10];
    const float* g3  = (const float*)d_in[11];
    const float* be3 = (const float*)d_in[12];
    const float* w4  = (const float*)d_in[13];
    const float* b4  = (const float*)d_in[14];
    const float* g4  = (const float*)d_in[15];
    const float* be4 = (const float*)d_in[16];
    const float* w5  = (const float*)d_in[17];
    const float* b5  = (const float*)d_in[18];
    const float* g5  = (const float*)d_in[19];
    const float* be5 = (const float*)d_in[20];
    const float* w6  = (const float*)d_in[21];
    const float* b6  = (const float*)d_in[22];
    const float* g6  = (const float*)d_in[23];
    const float* be6 = (const float*)d_in[24];
    const float* w7  = (const float*)d_in[25];
    const float* b7  = (const float*)d_in[26];
    const float* w8  = (const float*)d_in[27];
    const float* b8  = (const float*)d_in[28];
    const float* w9  = (const float*)d_in[29];
    const float* b9  = (const float*)d_in[30];
    float* out = (float*)d_out;

    float *h1, *h2, *h3, *h3t, *h4, *h5, *h6, *w8t, *P8, *y8, *y9, *gcon, *scale, *shift;
    int* idxp;
    cudaGetSymbolAddress((void**)&h1,    g_h1);
    cudaGetSymbolAddress((void**)&h2,    g_h2);
    cudaGetSymbolAddress((void**)&h3,    g_h3);
    cudaGetSymbolAddress((void**)&h3t,   g_h3t);
    cudaGetSymbolAddress((void**)&h4,    g_h4);
    cudaGetSymbolAddress((void**)&h5,    g_h5);
    cudaGetSymbolAddress((void**)&h6,    g_h6);
    cudaGetSymbolAddress((void**)&w8t,   g_w8t);
    cudaGetSymbolAddress((void**)&P8,    g_P8);
    cudaGetSymbolAddress((void**)&y8,    g_y8);
    cudaGetSymbolAddress((void**)&y9,    g_y9);
    cudaGetSymbolAddress((void**)&gcon,  g_gcon);
    cudaGetSymbolAddress((void**)&idxp,  g_idx);
    cudaGetSymbolAddress((void**)&scale, g_scale);
    cudaGetSymbolAddress((void**)&shift, g_shift);

    float* sc1 = scale + 0 * 512; float* sf1 = shift + 0 * 512;
    float* sc2 = scale + 1 * 512; float* sf2 = shift + 1 * 512;
    float* sc3 = scale + 2 * 512; float* sf3 = shift + 2 * 512;
    float* sc4 = scale + 3 * 512; float* sf4 = shift + 3 * 512;
    float* sc5 = scale + 4 * 512; float* sf5 = shift + 4 * 512;
    float* sc6 = scale + 5 * 512; float* sf6 = shift + 5 * 512;

    const int NB = NPTS / 64;

    // w8 permute can run first (independent)
    transpose_w8<<<dim3(8, 8, 256), dim3(32, 8)>>>(w8, w8t);

    // conv1 (4->64), raw out
    gemm_f32<<<dim3(NB, 1, B_), 256>>>(x, w1, b1, h1, 64, 4, NPTS, 4, nullptr, nullptr, 0);
    stats_kernel<<<64, 256>>>(h1, g1, be1, sc1, sf1, 64);

    // conv2 (64->128), bn1+relu fused on load
    gemm_f32<<<dim3(NB, 2, B_), 256>>>(h1, w2, b2, h2, 128, 64, NPTS, 64, sc1, sf1, 1);
    stats_kernel<<<128, 256>>>(h2, g2, be2, sc2, sf2, 128);

    // conv3 (128->256), bn2+relu fused
    gemm_f32<<<dim3(NB, 4, B_), 256>>>(h2, w3, b3, h3, 256, 128, NPTS, 128, sc2, sf2, 1);
    stats_kernel<<<256, 256>>>(h3, g3, be3, sc3, sf3, 256);

    // top-32 on raw h3 (order preserved under positive BN scale)
    topk_kernel<<<B_ * 256, 256>>>(h3, idxp);
    transpose_h3<<<dim3(128, 8, B_), dim3(32, 8)>>>(h3, h3t);

    // conv8 fused gather GEMM (bn3 applied in gather), split-K 16
    conv8_kernel<<<dim3(8, 16), 256>>>(h3t, w8t, idxp, sc3, sf3, P8);
    reduce8_kernel<<<(256 * 512) / 256, 256>>>(P8, b8, y8);

    // conv9 -> global feature
    conv9_kernel<<<B_ * 256, 256>>>(y8, w9, b9, y9);
    gcon_kernel<<<(B_ * 512) / 256, 256>>>(w4, y9, gcon);

    // conv4 (64->512) tf32, bn1+relu fused, + gcon
    gemm_tf32<<<dim3(NB, 4, B_), 256>>>(h1, w4 + 256, b4, gcon, h4, 512, 64, NPTS, 320,
                                        sc1, sf1, 1);
    stats_kernel<<<512, 256>>>(h4, g4, be4, sc4, sf4, 512);

    // conv5 (512->256) tf32, bn4+relu fused
    gemm_tf32<<<dim3(NB, 2, B_), 256>>>(h4, w5, b5, nullptr, h5, 256, 512, NPTS, 512,
                                        sc4, sf4, 1);
    stats_kernel<<<256, 256>>>(h5, g5, be5, sc5, sf5, 256);

    // conv6 (256->128) tf32, bn5+relu fused
    gemm_tf32<<<dim3(NB, 1, B_), 256>>>(h5, w6, b6, nullptr, h6, 128, 256, NPTS, 256,
                                        sc5, sf5, 1);
    stats_kernel<<<128, 256>>>(h6, g6, be6, sc6, sf6, 128);

    // conv7 (128->3) + bn6 + relu + tanh
    conv7_kernel<<<(B_ * NPTS) / 256, 256>>>(h6, sc6, sf6, w7, b7, out);
}

// round 5
// speedup vs baseline: 1.8497x; 1.1070x over previous
#include <cuda_runtime.h>
#include <math.h>
#include <float.h>
#include <stdint.h>

#define B_    16
#define NPTS  4096

// ---------------- scratch (static device globals) ---------------------------------
__device__ float g_h1[(size_t)B_ * 64  * NPTS];
__device__ float g_h2[(size_t)B_ * 128 * NPTS];
__device__ float g_h3[(size_t)B_ * 256 * NPTS];
__device__ float g_h3t[(size_t)B_ * NPTS * 256];   // [b][n][c]
__device__ float g_h4[(size_t)B_ * 512 * NPTS];
__device__ float g_h5[(size_t)B_ * 256 * NPTS];
__device__ float g_h6[(size_t)B_ * 128 * NPTS];
__device__ float g_w8t[(size_t)256 * 256 * 256];   // [w][c][o]
__device__ float g_P8[(size_t)16 * 256 * 512];     // split-K partials for conv8
__device__ float g_y8[256 * 512];                  // conv8 out, [o][b*32+h]
__device__ float g_y9[B_ * 512];
__device__ float g_gcon[B_ * 512];
__device__ int   g_idx[B_ * 256 * 32];
__device__ float g_scale[6 * 512];
__device__ float g_shift[6 * 512];
__device__ float g_part[512 * B_ * 2];             // stats partials [c][b][2]

__device__ __forceinline__ float f2tf32f(float f) {
    uint32_t u;
    asm("cvt.rna.tf32.f32 %0, %1;" : "=r"(u) : "f"(f));
    return __uint_as_float(u);
}

__device__ __forceinline__ void mma_tf32(float* d, const uint32_t* a, const uint32_t* b) {
    asm volatile(
        "mma.sync.aligned.m16n8k8.row.col.f32.tf32.tf32.f32 "
        "{%0,%1,%2,%3}, {%4,%5,%6,%7}, {%8,%9}, {%0,%1,%2,%3};"
        : "+f"(d[0]), "+f"(d[1]), "+f"(d[2]), "+f"(d[3])
        : "r"(a[0]), "r"(a[1]), "r"(a[2]), "r"(a[3]), "r"(b[0]), "r"(b[1]));
}

__device__ __forceinline__ void bn4(float4& v, float sc, float sf, int relu) {
    v.x = v.x * sc + sf; v.y = v.y * sc + sf;
    v.z = v.z * sc + sf; v.w = v.w * sc + sf;
    if (relu) {
        v.x = fmaxf(v.x, 0.f); v.y = fmaxf(v.y, 0.f);
        v.z = fmaxf(v.z, 0.f); v.w = fmaxf(v.w, 0.f);
    }
}

// ---------------- fp32 SGEMM 64x64 (conv1 only: K=4), BN fused on load -------------
__global__ void gemm_f32(const float* __restrict__ X, const float* __restrict__ W,
                         const float* __restrict__ bias, float* __restrict__ Y,
                         int O, int K, int N, int ldw,
                         const float* __restrict__ bnS, const float* __restrict__ bnF,
                         int relu)
{
    __shared__ float As[16][66];
    __shared__ float Bs[16][64];

    int b  = blockIdx.z;
    int o0 = blockIdx.y * 64;
    int n0 = blockIdx.x * 64;
    const float* Xb = X + (size_t)b * K * N;

    int tid = threadIdx.x;
    int tm  = tid >> 4;
    int tn  = tid & 15;

    float acc[4][4] = {};

    for (int k0 = 0; k0 < K; k0 += 16) {
        #pragma unroll
        for (int i = 0; i < 4; i++) {
            int e = tid + i * 256;
            int m = e >> 4, k = e & 15;
            As[k][m] = (k0 + k < K) ? W[(size_t)(o0 + m) * ldw + k0 + k] : 0.f;
        }
        #pragma unroll
        for (int i = 0; i < 4; i++) {
            int e = tid + i * 256;
            int k = e >> 6, n = e & 63;
            float v = 0.f;
            if (k0 + k < K) {
                v = Xb[(size_t)(k0 + k) * N + n0 + n];
                if (bnS) {
                    v = v * bnS[k0 + k] + bnF[k0 + k];
                    if (relu) v = fmaxf(v, 0.f);
                }
            }
            Bs[k][n] = v;
        }
        __syncthreads();
        #pragma unroll
        for (int kk = 0; kk < 16; kk++) {
            float a[4], bb[4];
            #pragma unroll
            for (int i = 0; i < 4; i++) a[i]  = As[kk][tm * 4 + i];
            #pragma unroll
            for (int j = 0; j < 4; j++) bb[j] = Bs[kk][tn * 4 + j];
            #pragma unroll
            for (int i = 0; i < 4; i++)
                #pragma unroll
                for (int j = 0; j < 4; j++)
                    acc[i][j] += a[i] * bb[j];
        }
        __syncthreads();
    }

    #pragma unroll
    for (int i = 0; i < 4; i++) {
        int o = o0 + tm * 4 + i;
        float bv = bias ? bias[o] : 0.f;
        size_t base = (size_t)(b * O + o) * N;
        #pragma unroll
        for (int j = 0; j < 4; j++)
            Y[base + n0 + tn * 4 + j] = acc[i][j] + bv;
    }
}

// ---------------- fp32 SGEMM 128x64, 8x4 micro (conv2, conv3 — exact, feed top-k) --
// K must be a multiple of 16; O multiple of 128.
__global__ void __launch_bounds__(256) gemm_f32_big(
    const float* __restrict__ X, const float* __restrict__ W,
    const float* __restrict__ bias, float* __restrict__ Y,
    int O, int K, int N, int ldw,
    const float* __restrict__ bnS, const float* __restrict__ bnF, int relu)
{
    __shared__ float As[16][132];  // [k][m]
    __shared__ float Bs[16][68];   // [k][n]

    int b  = blockIdx.z;
    int o0 = blockIdx.y * 128;
    int n0 = blockIdx.x * 64;
    const float* Xb = X + (size_t)b * K * N;

    int tid = threadIdx.x;
    int tm  = tid >> 4;     // 0..15 -> rows tm*8..+7
    int tn  = tid & 15;     // cols tn*4..+3

    int rowA = tid & 127;
    int kqA  = tid >> 7;    // 0 or 1 -> quads kqA, kqA+2
    const float* wp = W + (size_t)(o0 + rowA) * ldw;
    int krB = tid >> 4;     // 0..15
    int n4  = (tid & 15) * 4;

    float acc[8][4] = {};
    float4 ra0, ra1, rb;

    // preload k0 = 0
    ra0 = *(const float4*)(wp + kqA * 4);
    ra1 = *(const float4*)(wp + (kqA + 2) * 4);
    rb  = *(const float4*)(Xb + (size_t)krB * N + n0 + n4);

    int nIter = K / 16;
    for (int it = 0; it < nIter; it++) {
        // store current regs to smem
        As[kqA * 4 + 0][rowA] = ra0.x;
        As[kqA * 4 + 1][rowA] = ra0.y;
        As[kqA * 4 + 2][rowA] = ra0.z;
        As[kqA * 4 + 3][rowA] = ra0.w;
        As[(kqA + 2) * 4 + 0][rowA] = ra1.x;
        As[(kqA + 2) * 4 + 1][rowA] = ra1.y;
        As[(kqA + 2) * 4 + 2][rowA] = ra1.z;
        As[(kqA + 2) * 4 + 3][rowA] = ra1.w;
        {
            float4 v = rb;
            if (bnS) bn4(v, bnS[it * 16 + krB], bnF[it * 16 + krB], relu);
            *(float4*)&Bs[krB][n4] = v;
        }
        __syncthreads();

        if (it + 1 < nIter) {
            int k0 = (it + 1) * 16;
            ra0 = *(const float4*)(wp + k0 + kqA * 4);
            ra1 = *(const float4*)(wp + k0 + (kqA + 2) * 4);
            rb  = *(const float4*)(Xb + (size_t)(k0 + krB) * N + n0 + n4);
        }

        #pragma unroll
        for (int kk = 0; kk < 16; kk++) {
            float a[8], bb[4];
            *(float4*)&a[0] = *(const float4*)&As[kk][tm * 8];
            *(float4*)&a[4] = *(const float4*)&As[kk][tm * 8 + 4];
            *(float4*)&bb[0] = *(const float4*)&Bs[kk][tn * 4];
            #pragma unroll
            for (int i = 0; i < 8; i++)
                #pragma unroll
                for (int j = 0; j < 4; j++)
                    acc[i][j] += a[i] * bb[j];
        }
        __syncthreads();
    }

    #pragma unroll
    for (int i = 0; i < 8; i++) {
        int o = o0 + tm * 8 + i;
        float bv = bias ? bias[o] : 0.f;
        float4 v = make_float4(acc[i][0] + bv, acc[i][1] + bv,
                               acc[i][2] + bv, acc[i][3] + bv);
        *(float4*)&Y[(size_t)(b * O + o) * N + n0 + tn * 4] = v;
    }
}

// ---------------- tf32 tensor GEMM, 128x128 tile, warp tile 64x32, BN fused --------
// O multiple of 128, N multiple of 128, K multiple of 16.
__global__ void __launch_bounds__(256) gemm_tf32(
    const float* __restrict__ X, const float* __restrict__ W,
    const float* __restrict__ bias, const float* __restrict__ biasBO,
    float* __restrict__ Y, int O, int K, int N, int ldw,
    const float* __restrict__ bnS, const float* __restrict__ bnF, int relu)
{
    __shared__ float As[2][16][136];
    __shared__ float Bs[2][16][136];

    int b  = blockIdx.z;
    int o0 = blockIdx.y * 128;
    int n0 = blockIdx.x * 128;
    const float* Xb = X + (size_t)b * K * N;

    int tid  = threadIdx.x;
    int lane = tid & 31;
    int warp = tid >> 5;
    int wm   = (warp & 1) * 64;    // 2 warps over m
    int wn   = (warp >> 1) * 32;   // 4 warps over n
    int gid  = lane >> 2;
    int tig  = lane & 3;

    int rowA = tid & 127;
    int kqA  = tid >> 7;           // quads kqA, kqA+2
    const float* wp = W + (size_t)(o0 + rowA) * ldw;
    int krB = tid >> 5;            // 0..7 -> rows krB, krB+8
    int n4  = (tid & 31) * 4;

    float acc[4][4][4] = {};
    float4 ra0, ra1, rb0, rb1;

    // prologue fetch + store stage 0
    {
        ra0 = *(const float4*)(wp + kqA * 4);
        ra1 = *(const float4*)(wp + (kqA + 2) * 4);
        rb0 = *(const float4*)(Xb + (size_t)krB * N + n0 + n4);
        rb1 = *(const float4*)(Xb + (size_t)(krB + 8) * N + n0 + n4);
        if (bnS) {
            bn4(rb0, bnS[krB], bnF[krB], relu);
            bn4(rb1, bnS[krB + 8], bnF[krB + 8], relu);
        }
        As[0][kqA*4+0][rowA] = f2tf32f(ra0.x);
        As[0][kqA*4+1][rowA] = f2tf32f(ra0.y);
        As[0][kqA*4+2][rowA] = f2tf32f(ra0.z);
        As[0][kqA*4+3][rowA] = f2tf32f(ra0.w);
        As[0][(kqA+2)*4+0][rowA] = f2tf32f(ra1.x);
        As[0][(kqA+2)*4+1][rowA] = f2tf32f(ra1.y);
        As[0][(kqA+2)*4+2][rowA] = f2tf32f(ra1.z);
        As[0][(kqA+2)*4+3][rowA] = f2tf32f(ra1.w);
        *(float4*)&Bs[0][krB][n4] =
            make_float4(f2tf32f(rb0.x), f2tf32f(rb0.y), f2tf32f(rb0.z), f2tf32f(rb0.w));
        *(float4*)&Bs[0][krB + 8][n4] =
            make_float4(f2tf32f(rb1.x), f2tf32f(rb1.y), f2tf32f(rb1.z), f2tf32f(rb1.w));
    }
    __syncthreads();

    int nIter = K / 16;
    for (int it = 0; it < nIter; it++) {
        int s = it & 1;
        bool more = (it + 1 < nIter);
        if (more) {
            int k0 = (it + 1) * 16;
            ra0 = *(const float4*)(wp + k0 + kqA * 4);
            ra1 = *(const float4*)(wp + k0 + (kqA + 2) * 4);
            rb0 = *(const float4*)(Xb + (size_t)(k0 + krB) * N + n0 + n4);
            rb1 = *(const float4*)(Xb + (size_t)(k0 + krB + 8) * N + n0 + n4);
            if (bnS) {
                bn4(rb0, bnS[k0 + krB], bnF[k0 + krB], relu);
                bn4(rb1, bnS[k0 + krB + 8], bnF[k0 + krB + 8], relu);
            }
        }

        #pragma unroll
        for (int ks = 0; ks < 2; ks++) {
            int kk = ks * 8;
            uint32_t a[4][4], bf[4][2];
            #pragma unroll
            for (int i = 0; i < 4; i++) {
                int mr = wm + i * 16 + gid;
                a[i][0] = __float_as_uint(As[s][kk + tig    ][mr    ]);
                a[i][1] = __float_as_uint(As[s][kk + tig    ][mr + 8]);
                a[i][2] = __float_as_uint(As[s][kk + tig + 4][mr    ]);
                a[i][3] = __float_as_uint(As[s][kk + tig + 4][mr + 8]);
            }
            #pragma unroll
            for (int j = 0; j < 4; j++) {
                int nc = wn + j * 8 + gid;
                bf[j][0] = __float_as_uint(Bs[s][kk + tig    ][nc]);
                bf[j][1] = __float_as_uint(Bs[s][kk + tig + 4][nc]);
            }
            #pragma unroll
            for (int i = 0; i < 4; i++)
                #pragma unroll
                for (int j = 0; j < 4; j++)
                    mma_tf32(acc[i][j], a[i], bf[j]);
        }

        if (more) {
            int d = s ^ 1;
            As[d][kqA*4+0][rowA] = f2tf32f(ra0.x);
            As[d][kqA*4+1][rowA] = f2tf32f(ra0.y);
            As[d][kqA*4+2][rowA] = f2tf32f(ra0.z);
            As[d][kqA*4+3][rowA] = f2tf32f(ra0.w);
            As[d][(kqA+2)*4+0][rowA] = f2tf32f(ra1.x);
            As[d][(kqA+2)*4+1][rowA] = f2tf32f(ra1.y);
            As[d][(kqA+2)*4+2][rowA] = f2tf32f(ra1.z);
            As[d][(kqA+2)*4+3][rowA] = f2tf32f(ra1.w);
            *(float4*)&Bs[d][krB][n4] =
                make_float4(f2tf32f(rb0.x), f2tf32f(rb0.y), f2tf32f(rb0.z), f2tf32f(rb0.w));
            *(float4*)&Bs[d][krB + 8][n4] =
                make_float4(f2tf32f(rb1.x), f2tf32f(rb1.y), f2tf32f(rb1.z), f2tf32f(rb1.w));
        }
        __syncthreads();
    }

    #pragma unroll
    for (int i = 0; i < 4; i++) {
        int r0 = o0 + wm + i * 16 + gid;
        int r1 = r0 + 8;
        float bv0 = 0.f, bv1 = 0.f;
        if (bias)   { bv0 += bias[r0]; bv1 += bias[r1]; }
        if (biasBO) { bv0 += biasBO[b * O + r0]; bv1 += biasBO[b * O + r1]; }
        size_t base0 = (size_t)(b * O + r0) * N;
        size_t base1 = (size_t)(b * O + r1) * N;
        #pragma unroll
        for (int j = 0; j < 4; j++) {
            int c = n0 + wn + j * 8 + 2 * tig;
            *(float2*)&Y[base0 + c] = make_float2(acc[i][j][0] + bv0, acc[i][j][1] + bv0);
            *(float2*)&Y[base1 + c] = make_float2(acc[i][j][2] + bv1, acc[i][j][3] + bv1);
        }
    }
}

// ---------------- conv8 fused gather GEMM ------------------------------------------
__global__ void __launch_bounds__(256) conv8_kernel(
    const float* __restrict__ h3t, const float* __restrict__ w8tt,
    const int* __restrict__ idx, const float* __restrict__ sc3,
    const float* __restrict__ sf3, float* __restrict__ P8)
{
    __shared__ float As[2][16][264];
    __shared__ float Bs[2][16][72];
    __shared__ int   sIdx[1024];

    int col0  = blockIdx.x * 64;
    int chunk = blockIdx.y;
    int tid = threadIdx.x;
    int lane = tid & 31, warp = tid >> 5;
    int wm = warp * 32;
    int gid = lane >> 2, tig = lane & 3;

    #pragma unroll
    for (int i = 0; i < 4; i++) {
        int e = tid + i * 256;
        int w16 = e >> 6, j = e & 63;
        int col = col0 + j, b = col >> 5, h = col & 31;
        sIdx[e] = idx[(((b << 8) + (chunk * 16 + w16)) << 5) + h];
    }
    __syncthreads();

    int jB = tid >> 2, cq = tid & 3;
    const float* h3b = h3t + ((size_t)((col0 + jB) >> 5) << 20);

    int kA = tid >> 4;
    int oA = (tid & 15) * 16;
    const float* abase = w8tt + (size_t)chunk * 4096 * 256;

    float acc[2][8][4] = {};
    float4 a0, a1, a2, a3, bv, scv, sfv;

    {
        const float* ap = abase + (size_t)kA * 256 + oA;
        a0 = *(const float4*)(ap);
        a1 = *(const float4*)(ap + 4);
        a2 = *(const float4*)(ap + 8);
        a3 = *(const float4*)(ap + 12);
        int n = sIdx[jB];
        bv  = *(const float4*)(h3b + ((size_t)n << 8) + cq * 4);
        scv = *(const float4*)(sc3 + cq * 4);
        sfv = *(const float4*)(sf3 + cq * 4);
    }
    {
        float* ar = &As[0][kA][oA];
        *(float4*)(ar)      = make_float4(f2tf32f(a0.x), f2tf32f(a0.y), f2tf32f(a0.z), f2tf32f(a0.w));
        *(float4*)(ar + 4)  = make_float4(f2tf32f(a1.x), f2tf32f(a1.y), f2tf32f(a1.z), f2tf32f(a1.w));
        *(float4*)(ar + 8)  = make_float4(f2tf32f(a2.x), f2tf32f(a2.y), f2tf32f(a2.z), f2tf32f(a2.w));
        *(float4*)(ar + 12) = make_float4(f2tf32f(a3.x), f2tf32f(a3.y), f2tf32f(a3.z), f2tf32f(a3.w));
        Bs[0][cq*4+0][jB] = f2tf32f(bv.x * scv.x + sfv.x);
        Bs[0][cq*4+1][jB] = f2tf32f(bv.y * scv.y + sfv.y);
        Bs[0][cq*4+2][jB] = f2tf32f(bv.z * scv.z + sfv.z);
        Bs[0][cq*4+3][jB] = f2tf32f(bv.w * scv.w + sfv.w);
    }
    __syncthreads();

    for (int t = 0; t < 256; t++) {
        int s = t & 1;
        bool more = (t < 255);
        if (more) {
            int t1 = t + 1;
            int w16 = t1 >> 4, c0 = (t1 & 15) * 16;
            const float* ap = abase + (size_t)(w16 * 256 + c0 + kA) * 256 + oA;
            a0 = *(const float4*)(ap);
            a1 = *(const float4*)(ap + 4);
            a2 = *(const float4*)(ap + 8);
            a3 = *(const float4*)(ap + 12);
            int n = sIdx[w16 * 64 + jB];
            bv  = *(const float4*)(h3b + ((size_t)n << 8) + c0 + cq * 4);
            scv = *(const float4*)(sc3 + c0 + cq * 4);
            sfv = *(const float4*)(sf3 + c0 + cq * 4);
        }

        #pragma unroll
        for (int ks = 0; ks < 2; ks++) {
            int kk = ks * 8;
            uint32_t a[2][4], bf[8][2];
            #pragma unroll
            for (int i = 0; i < 2; i++) {
                int mr = wm + i * 16 + gid;
                a[i][0] = __float_as_uint(As[s][kk + tig    ][mr    ]);
                a[i][1] = __float_as_uint(As[s][kk + tig    ][mr + 8]);
                a[i][2] = __float_as_uint(As[s][kk + tig + 4][mr    ]);
                a[i][3] = __float_as_uint(As[s][kk + tig + 4][mr + 8]);
            }
            #pragma unroll
            for (int j = 0; j < 8; j++) {
                int nc = j * 8 + gid;
                bf[j][0] = __float_as_uint(Bs[s][kk + tig    ][nc]);
                bf[j][1] = __float_as_uint(Bs[s][kk + tig + 4][nc]);
            }
            #pragma unroll
            for (int i = 0; i < 2; i++)
                #pragma unroll
                for (int j = 0; j < 8; j++)
                    mma_tf32(acc[i][j], a[i], bf[j]);
        }

        if (more) {
            int d = s ^ 1;
            float* ar = &As[d][kA][oA];
            *(float4*)(ar)      = make_float4(f2tf32f(a0.x), f2tf32f(a0.y), f2tf32f(a0.z), f2tf32f(a0.w));
            *(float4*)(ar + 4)  = make_float4(f2tf32f(a1.x), f2tf32f(a1.y), f2tf32f(a1.z), f2tf32f(a1.w));
            *(float4*)(ar + 8)  = make_float4(f2tf32f(a2.x), f2tf32f(a2.y), f2tf32f(a2.z), f2tf32f(a2.w));
            *(float4*)(ar + 12) = make_float4(f2tf32f(a3.x), f2tf32f(a3.y), f2tf32f(a3.z), f2tf32f(a3.w));
            Bs[d][cq*4+0][jB] = f2tf32f(bv.x * scv.x + sfv.x);
            Bs[d][cq*4+1][jB] = f2tf32f(bv.y * scv.y + sfv.y);
            Bs[d][cq*4+2][jB] = f2tf32f(bv.z * scv.z + sfv.z);
            Bs[d][cq*4+3][jB] = f2tf32f(bv.w * scv.w + sfv.w);
        }
        __syncthreads();
    }

    #pragma unroll
    for (int i = 0; i < 2; i++) {
        int r0 = wm + i * 16 + gid;
        size_t base0 = ((size_t)chunk * 256 + r0) * 512 + col0;
        size_t base1 = ((size_t)chunk * 256 + r0 + 8) * 512 + col0;
        #pragma unroll
        for (int j = 0; j < 8; j++) {
            int c = j * 8 + 2 * tig;
            *(float2*)&P8[base0 + c] = make_float2(acc[i][j][0], acc[i][j][1]);
            *(float2*)&P8[base1 + c] = make_float2(acc[i][j][2], acc[i][j][3]);
        }
    }
}

// ---------------- transposes -------------------------------------------------------
__global__ void transpose_h3(const float* __restrict__ src, float* __restrict__ dst)
{
    __shared__ float s[32][33];
    int b = blockIdx.z, n0 = blockIdx.x * 32, c0 = blockIdx.y * 32;
    int tx = threadIdx.x, ty = threadIdx.y;
    const float* sb = src + ((size_t)b << 20);
    float* db = dst + ((size_t)b << 20);
    #pragma unroll
    for (int k = 0; k < 4; k++)
        s[ty + 8 * k][tx] = sb[(size_t)(c0 + ty + 8 * k) * 4096 + n0 + tx];
    __syncthreads();
    #pragma unroll
    for (int k = 0; k < 4; k++)
        db[(size_t)(n0 + ty + 8 * k) * 256 + c0 + tx] = s[tx][ty + 8 * k];
}

__global__ void transpose_w8(const float* __restrict__ src, float* __restrict__ dst)
{
    __shared__ float s[32][33];
    int c = blockIdx.z, o0 = blockIdx.y * 32, w0 = blockIdx.x * 32;
    int tx = threadIdx.x, ty = threadIdx.y;
    #pragma unroll
    for (int k = 0; k < 4; k++)
        s[ty + 8 * k][tx] = src[(size_t)(o0 + ty + 8 * k) * 65536 + c * 256 + w0 + tx];
    __syncthreads();
    #pragma unroll
    for (int k = 0; k < 4; k++)
        dst[(size_t)(w0 + ty + 8 * k) * 65536 + c * 256 + o0 + tx] = s[tx][ty + 8 * k];
}

// ---------------- BN statistics: parallel partial pass + finalize -------------------
__global__ void stats_part(const float* __restrict__ X, float* __restrict__ part, int C)
{
    int c = blockIdx.x, b = blockIdx.y;
    const float* p = X + ((size_t)(b * C + c)) * NPTS;
    float s = 0.f, s2 = 0.f;
    for (int t = threadIdx.x; t < NPTS / 4; t += blockDim.x) {
        float4 v = *(const float4*)&p[t * 4];
        s  += v.x + v.y + v.z + v.w;
        s2 += v.x * v.x + v.y * v.y + v.z * v.z + v.w * v.w;
    }
    __shared__ float sh1[256], sh2[256];
    sh1[threadIdx.x] = s; sh2[threadIdx.x] = s2;
    __syncthreads();
    for (int st = 128; st > 0; st >>= 1) {
        if (threadIdx.x < st) {
            sh1[threadIdx.x] += sh1[threadIdx.x + st];
            sh2[threadIdx.x] += sh2[threadIdx.x + st];
        }
        __syncthreads();
    }
    if (threadIdx.x == 0) {
        part[(c * B_ + b) * 2 + 0] = sh1[0];
        part[(c * B_ + b) * 2 + 1] = sh2[0];
    }
}

__global__ void stats_fin(const float* __restrict__ part, const float* __restrict__ g,
                          const float* __restrict__ be,
                          float* __restrict__ scale, float* __restrict__ shift, int C)
{
    int c = blockIdx.x * blockDim.x + threadIdx.x;
    if (c >= C) return;
    float s = 0.f, s2 = 0.f;
    #pragma unroll
    for (int b = 0; b < B_; b++) {
        s  += part[(c * B_ + b) * 2 + 0];
        s2 += part[(c * B_ + b) * 2 + 1];
    }
    const float inv = 1.f / (float)(B_ * NPTS);
    float m  = s * inv;
    float v  = s2 * inv - m * m;
    float sc = g[c] / sqrtf(v + 1e-5f);
    scale[c] = sc;
    shift[c] = be[c] - m * sc;
}

// ---------------- exact top-32 per (b,c) row ---------------------------------------
__global__ void topk_kernel(const float* __restrict__ X, int* __restrict__ idx_out)
{
    int bc = blockIdx.x;
    const float* row = X + (size_t)bc * NPTS;
    int tid = threadIdx.x;

    float v[16];
    #pragma unroll
    for (int j = 0; j < 16; j++) v[j] = row[j * 256 + tid];

    __shared__ float swv[8];
    __shared__ int   swi[8];
    __shared__ int   sbi;

    for (int iter = 0; iter < 32; iter++) {
        float lv = -FLT_MAX; int li = 0x7fffffff;
        #pragma unroll
        for (int j = 0; j < 16; j++) {
            int n = j * 256 + tid;
            if (v[j] > lv || (v[j] == lv && n < li)) { lv = v[j]; li = n; }
        }
        #pragma unroll
        for (int off = 16; off > 0; off >>= 1) {
            float ov = __shfl_down_sync(0xffffffff, lv, off);
            int   oi = __shfl_down_sync(0xffffffff, li, off);
            if (ov > lv || (ov == lv && oi < li)) { lv = ov; li = oi; }
        }
        if ((tid & 31) == 0) { swv[tid >> 5] = lv; swi[tid >> 5] = li; }
        __syncthreads();
        if (tid == 0) {
            float gv = swv[0]; int gi = swi[0];
            #pragma unroll
            for (int w = 1; w < 8; w++)
                if (swv[w] > gv || (swv[w] == gv && swi[w] < gi)) { gv = swv[w]; gi = swi[w]; }
            sbi = gi;
            idx_out[bc * 32 + iter] = gi;
        }
        __syncthreads();
        int gi = sbi;
        if ((gi & 255) == tid) v[gi >> 8] = -FLT_MAX;
        __syncthreads();
    }
}

// ---------------- conv8 split-K reduce ---------------------------------------------
__global__ void reduce8_kernel(const float* __restrict__ P, const float* __restrict__ b8,
                               float* __restrict__ y8)
{
    int i = blockIdx.x * blockDim.x + threadIdx.x;
    float s = b8[i >> 9];
    #pragma unroll
    for (int ch = 0; ch < 16; ch++) s += P[(size_t)ch * 131072 + i];
    y8[i] = s;
}

// ---------------- conv9 ------------------------------------------------------------
__global__ void conv9_kernel(const float* __restrict__ y8, const float* __restrict__ w9,
                             const float* __restrict__ b9, float* __restrict__ y9)
{
    int b = blockIdx.x >> 8;
    int o = blockIdx.x & 255;
    int c = threadIdx.x;
    float s = 0.f;
    const float* yb = y8 + (size_t)c * 512 + b * 32;
    const float* wr = w9 + ((size_t)o * 256 + c) * 32;
    #pragma unroll
    for (int h = 0; h < 32; h++) s += yb[h] * wr[h];
    __shared__ float sh[256];
    sh[c] = s; __syncthreads();
    for (int st = 128; st > 0; st >>= 1) {
        if (c < st) sh[c] += sh[c + st];
        __syncthreads();
    }
    if (c == 0) y9[b * 256 + o] = sh[0] + b9[o];
}

// ---------------- glob contribution to conv4 ---------------------------------------
__global__ void gcon_kernel(const float* __restrict__ w4, const float* __restrict__ y9,
                            float* __restrict__ gcon)
{
    int i = blockIdx.x * blockDim.x + threadIdx.x;
    int b = i >> 9, o = i & 511;
    float s = 0.f;
    for (int c = 0; c < 256; c++) s += w4[o * 320 + c] * y9[b * 256 + c];
    gcon[i] = s;
}

// ---------------- conv7 + bn6 + relu + tanh ----------------------------------------
__global__ void conv7_kernel(const float* __restrict__ h6, const float* __restrict__ sc,
                             const float* __restrict__ sf, const float* __restrict__ w7,
                             const float* __restrict__ b7, float* __restrict__ out)
{
    int i = blockIdx.x * blockDim.x + threadIdx.x;
    int b = i >> 12, n = i & (NPTS - 1);
    float s0 = b7[0], s1 = b7[1], s2 = b7[2];
    const float* hb = h6 + (((size_t)b * 128) << 12) + n;
    for (int c = 0; c < 128; c++) {
        float v = fmaxf(hb[(size_t)c * NPTS] * sc[c] + sf[c], 0.f);
        s0 += w7[c] * v;
        s1 += w7[128 + c] * v;
        s2 += w7[256 + c] * v;
    }
    out[((size_t)(b * 3 + 0)) * NPTS + n] = tanhf(s0);
    out[((size_t)(b * 3 + 1)) * NPTS + n] = tanhf(s1);
    out[((size_t)(b * 3 + 2)) * NPTS + n] = tanhf(s2);
}

// ===================================================================================
extern "C" void kernel_launch(void* const* d_in, const int* in_sizes, int n_in,
                              void* d_out, int out_size)
{
    const float* x   = (const float*)d_in[0];
    const float* w1  = (const float*)d_in[1];
    const float* b1  = (const float*)d_in[2];
    const float* g1  = (const float*)d_in[3];
    const float* be1 = (const float*)d_in[4];
    const float* w2  = (const float*)d_in[5];
    const float* b2  = (const float*)d_in[6];
    const float* g2  = (const float*)d_in[7];
    const float* be2 = (const float*)d_in[8];
    const float* w3  = (const float*)d_in[9];
    const float* b3  = (const float*)d_in[10];
    const float* g3  = (const float*)d_in[11];
    const float* be3 = (const float*)d_in[12];
    const float* w4  = (const float*)d_in[13];
    const float* b4  = (const float*)d_in[14];
    const float* g4  = (const float*)d_in[15];
    const float* be4 = (const float*)d_in[16];
    const float* w5  = (const float*)d_in[17];
    const float* b5  = (const float*)d_in[18];
    const float* g5  = (const float*)d_in[19];
    const float* be5 = (const float*)d_in[20];
    const float* w6  = (const float*)d_in[21];
    const float* b6  = (const float*)d_in[22];
    const float* g6  = (const float*)d_in[23];
    const float* be6 = (const float*)d_in[24];
    const float* w7  = (const float*)d_in[25];
    const float* b7  = (const float*)d_in[26];
    const float* w8  = (const float*)d_in[27];
    const float* b8  = (const float*)d_in[28];
    const float* w9  = (const float*)d_in[29];
    const float* b9  = (const float*)d_in[30];
    float* out = (float*)d_out;

    float *h1, *h2, *h3, *h3t, *h4, *h5, *h6, *w8t, *P8, *y8, *y9, *gcon, *scale, *shift, *part;
    int* idxp;
    cudaGetSymbolAddress((void**)&h1,    g_h1);
    cudaGetSymbolAddress((void**)&h2,    g_h2);
    cudaGetSymbolAddress((void**)&h3,    g_h3);
    cudaGetSymbolAddress((void**)&h3t,   g_h3t);
    cudaGetSymbolAddress((void**)&h4,    g_h4);
    cudaGetSymbolAddress((void**)&h5,    g_h5);
    cudaGetSymbolAddress((void**)&h6,    g_h6);
    cudaGetSymbolAddress((void**)&w8t,   g_w8t);
    cudaGetSymbolAddress((void**)&P8,    g_P8);
    cudaGetSymbolAddress((void**)&y8,    g_y8);
    cudaGetSymbolAddress((void**)&y9,    g_y9);
    cudaGetSymbolAddress((void**)&gcon,  g_gcon);
    cudaGetSymbolAddress((void**)&idxp,  g_idx);
    cudaGetSymbolAddress((void**)&scale, g_scale);
    cudaGetSymbolAddress((void**)&shift, g_shift);
    cudaGetSymbolAddress((void**)&part,  g_part);

    float* sc1 = scale + 0 * 512; float* sf1 = shift + 0 * 512;
    float* sc2 = scale + 1 * 512; float* sf2 = shift + 1 * 512;
    float* sc3 = scale + 2 * 512; float* sf3 = shift + 2 * 512;
    float* sc4 = scale + 3 * 512; float* sf4 = shift + 3 * 512;
    float* sc5 = scale + 4 * 512; float* sf5 = shift + 4 * 512;
    float* sc6 = scale + 5 * 512; float* sf6 = shift + 5 * 512;

    transpose_w8<<<dim3(8, 8, 256), dim3(32, 8)>>>(w8, w8t);

    // conv1 (4->64), raw out (exact fp32, tiny K)
    gemm_f32<<<dim3(64, 1, B_), 256>>>(x, w1, b1, h1, 64, 4, NPTS, 4, nullptr, nullptr, 0);
    stats_part<<<dim3(64, B_), 256>>>(h1, part, 64);
    stats_fin<<<1, 64>>>(part, g1, be1, sc1, sf1, 64);

    // conv2 (64->128), bn1+relu fused, exact fp32
    gemm_f32_big<<<dim3(64, 1, B_), 256>>>(h1, w2, b2, h2, 128, 64, NPTS, 64, sc1, sf1, 1);
    stats_part<<<dim3(128, B_), 256>>>(h2, part, 128);
    stats_fin<<<1, 128>>>(part, g2, be2, sc2, sf2, 128);

    // conv3 (128->256), bn2+relu fused, exact fp32 (feeds top-k)
    gemm_f32_big<<<dim3(64, 2, B_), 256>>>(h2, w3, b3, h3, 256, 128, NPTS, 128, sc2, sf2, 1);
    stats_part<<<dim3(256, B_), 256>>>(h3, part, 256);
    stats_fin<<<1, 256>>>(part, g3, be3, sc3, sf3, 256);

    // top-32 on raw h3 (order preserved under positive BN scale)
    topk_kernel<<<B_ * 256, 256>>>(h3, idxp);
    transpose_h3<<<dim3(128, 8, B_), dim3(32, 8)>>>(h3, h3t);

    // conv8 fused gather GEMM (bn3 applied in gather), split-K 16
    conv8_kernel<<<dim3(8, 16), 256>>>(h3t, w8t, idxp, sc3, sf3, P8);
    reduce8_kernel<<<(256 * 512) / 256, 256>>>(P8, b8, y8);

    conv9_kernel<<<B_ * 256, 256>>>(y8, w9, b9, y9);
    gcon_kernel<<<(B_ * 512) / 256, 256>>>(w4, y9, gcon);

    // conv4 (64->512) tf32 128x128, bn1+relu fused, + gcon
    gemm_tf32<<<dim3(32, 4, B_), 256>>>(h1, w4 + 256, b4, gcon, h4, 512, 64, NPTS, 320,
                                        sc1, sf1, 1);
    stats_part<<<dim3(512, B_), 256>>>(h4, part, 512);
    stats_fin<<<1, 512>>>(part, g4, be4, sc4, sf4, 512);

    // conv5 (512->256) tf32 128x128, bn4+relu fused
    gemm_tf32<<<dim3(32, 2, B_), 256>>>(h4, w5, b5, nullptr, h5, 256, 512, NPTS, 512,
                                        sc4, sf4, 1);
    stats_part<<<dim3(256, B_), 256>>>(h5, part, 256);
    stats_fin<<<1, 256>>>(part, g5, be5, sc5, sf5, 256);

    // conv6 (256->128) tf32 128x128, bn5+relu fused
    gemm_tf32<<<dim3(32, 1, B_), 256>>>(h5, w6, b6, nullptr, h6, 128, 256, NPTS, 256,
                                        sc5, sf5, 1);
    stats_part<<<dim3(128, B_), 256>>>(h6, part, 128);
    stats_fin<<<1, 128>>>(part, g6, be6, sc6, sf6, 128);

    // conv7 (128->3) + bn6 + relu + tanh
    conv7_kernel<<<(B_ * NPTS) / 256, 256>>>(h6, sc6, sf6, w7, b7, out);
}